// round 10
// baseline (speedup 1.0000x reference)
#include <cuda_runtime.h>
#include <cstdint>

#define NN  50000
#define NE  800000
#define DD  64
#define HID 64

// Scratch: aggregation buffer (allocation-free rule -> __device__ global)
__device__ float g_agg[NN * DD];

__device__ __forceinline__ float silu_f(float v) {
    return v * (1.0f / (1.0f + __expf(-v)));
}

// ---------------- packed f32x2 helpers (Blackwell FFMA2) --------------------
__device__ __forceinline__ uint64_t dupf(float x) {
    uint64_t r; asm("mov.b64 %0, {%1, %1};" : "=l"(r) : "f"(x)); return r;
}
__device__ __forceinline__ void fma2(uint64_t& d, uint64_t a, uint64_t b) {
    asm("fma.rn.f32x2 %0, %1, %2, %0;" : "+l"(d) : "l"(a), "l"(b));
}
__device__ __forceinline__ float2 unpk(uint64_t v) {
    float2 f; asm("mov.b64 {%0, %1}, %2;" : "=f"(f.x), "=f"(f.y) : "l"(v)); return f;
}

// ---------------------------------------------------------------------------
// zero the aggregation scratch (must run every replay)
// ---------------------------------------------------------------------------
__global__ void zero_agg_kernel() {
    int i = blockIdx.x * blockDim.x + threadIdx.x;
    ((float4*)g_agg)[i] = make_float4(0.f, 0.f, 0.f, 0.f);
}

// ---------------------------------------------------------------------------
// Edge kernel: mij = silu(silu([h[row],h[col]]@W1+b1)@W2+b2); agg[row] += mij
// 64 edges per block, 128 threads, 4x8 micro-tiles via packed FFMA2.
// Weight pairs loaded as ulonglong2 (LDS.128 -> aligned reg pairs, no MOVs).
// ---------------------------------------------------------------------------
#define EDGE_SMEM ((64*128 + 128*64 + 64*64 + 64*68) * 4 + 2 * 64 * 4)

__global__ void __launch_bounds__(128, 2) edge_kernel(
    const float* __restrict__ h, const int* __restrict__ erow, const int* __restrict__ ecol,
    const float* __restrict__ W1, const float* __restrict__ b1,
    const float* __restrict__ W2, const float* __restrict__ b2,
    float* __restrict__ mij)
{
    extern __shared__ float sm[];
    float* Xs  = sm;                     // 64 x 128
    float* W1s = Xs + 64 * 128;          // 128 x 64
    float* W2s = W1s + 128 * 64;         // 64 x 64
    float* Hs  = W2s + 64 * 64;          // 64 x 68 (padded)
    int*   irs = (int*)(Hs + 64 * 68);   // 64 row ids
    int*   ics = irs + 64;               // 64 col ids

    const int tid = threadIdx.x;
    const int eb  = blockIdx.x * 64;

    if (tid < 64) irs[tid]      = erow[eb + tid];
    else          ics[tid - 64] = ecol[eb + tid - 64];
    __syncthreads();

    // gather X = [h[row] | h[col]] as float4 (2048 float4, 16 per thread)
    const float4* h4 = (const float4*)h;
    float4* X4 = (float4*)Xs;
#pragma unroll
    for (int i = 0; i < 16; i++) {
        int f = i * 128 + tid;
        int r = f >> 5, p = f & 31;
        int node = (p < 16) ? irs[r] : ics[r];
        X4[f] = h4[node * 16 + (p & 15)];
    }
    // stage W1 (2048 float4) and W2 (1024 float4) upfront
#pragma unroll
    for (int i = 0; i < 16; i++)
        ((float4*)W1s)[i * 128 + tid] = ((const float4*)W1)[i * 128 + tid];
#pragma unroll
    for (int i = 0; i < 8; i++)
        ((float4*)W2s)[i * 128 + tid] = ((const float4*)W2)[i * 128 + tid];
    __syncthreads();

    const int tx = tid & 7, ty = tid >> 3;   // 8 col-groups x 16 row-groups
    const int r0 = ty * 4, c0 = tx * 8;      // 4 rows x 8 cols per thread

    // acc[i][j]: row r0+i, column pair (c0+2j, c0+2j+1)
    uint64_t acc[4][4];
#pragma unroll
    for (int i = 0; i < 4; i++)
#pragma unroll
        for (int j = 0; j < 4; j++) acc[i][j] = 0ull;

    // layer 1: [64x128] @ [128x64]
#pragma unroll 4
    for (int k = 0; k < 128; k++) {
        ulonglong2 wA = *(const ulonglong2*)&W1s[k * 64 + c0];
        ulonglong2 wB = *(const ulonglong2*)&W1s[k * 64 + c0 + 4];
#pragma unroll
        for (int i = 0; i < 4; i++) {
            uint64_t xa = dupf(Xs[(r0 + i) * 128 + k]);
            fma2(acc[i][0], xa, wA.x);
            fma2(acc[i][1], xa, wA.y);
            fma2(acc[i][2], xa, wB.x);
            fma2(acc[i][3], xa, wB.y);
        }
    }
    {
        float4 bb0 = *(const float4*)&b1[c0];
        float4 bb1 = *(const float4*)&b1[c0 + 4];
#pragma unroll
        for (int i = 0; i < 4; i++) {
            float2 p0 = unpk(acc[i][0]), p1 = unpk(acc[i][1]);
            float2 p2 = unpk(acc[i][2]), p3 = unpk(acc[i][3]);
            float4 v0, v1;
            v0.x = silu_f(p0.x + bb0.x); v0.y = silu_f(p0.y + bb0.y);
            v0.z = silu_f(p1.x + bb0.z); v0.w = silu_f(p1.y + bb0.w);
            v1.x = silu_f(p2.x + bb1.x); v1.y = silu_f(p2.y + bb1.y);
            v1.z = silu_f(p3.x + bb1.z); v1.w = silu_f(p3.y + bb1.w);
            *(float4*)&Hs[(r0 + i) * 68 + c0]     = v0;
            *(float4*)&Hs[(r0 + i) * 68 + c0 + 4] = v1;
        }
    }
    __syncthreads();

#pragma unroll
    for (int i = 0; i < 4; i++)
#pragma unroll
        for (int j = 0; j < 4; j++) acc[i][j] = 0ull;

    // layer 2: [64x64] @ [64x64]
#pragma unroll 4
    for (int k = 0; k < 64; k++) {
        ulonglong2 wA = *(const ulonglong2*)&W2s[k * 64 + c0];
        ulonglong2 wB = *(const ulonglong2*)&W2s[k * 64 + c0 + 4];
#pragma unroll
        for (int i = 0; i < 4; i++) {
            uint64_t xa = dupf(Hs[(r0 + i) * 68 + k]);
            fma2(acc[i][0], xa, wA.x);
            fma2(acc[i][1], xa, wA.y);
            fma2(acc[i][2], xa, wB.x);
            fma2(acc[i][3], xa, wB.y);
        }
    }
    float4 b20 = *(const float4*)&b2[c0];
    float4 b21 = *(const float4*)&b2[c0 + 4];
#pragma unroll
    for (int i = 0; i < 4; i++) {
        float2 p0 = unpk(acc[i][0]), p1 = unpk(acc[i][1]);
        float2 p2 = unpk(acc[i][2]), p3 = unpk(acc[i][3]);
        float4 m0, m1;
        m0.x = silu_f(p0.x + b20.x); m0.y = silu_f(p0.y + b20.y);
        m0.z = silu_f(p1.x + b20.z); m0.w = silu_f(p1.y + b20.w);
        m1.x = silu_f(p2.x + b21.x); m1.y = silu_f(p2.y + b21.y);
        m1.z = silu_f(p3.x + b21.z); m1.w = silu_f(p3.y + b21.w);
        size_t ge = (size_t)(eb + r0 + i);
        *(float4*)&mij[ge * 64 + c0]     = m0;
        *(float4*)&mij[ge * 64 + c0 + 4] = m1;
        float* ap = &g_agg[(size_t)irs[r0 + i] * 64 + c0];
        asm volatile("red.global.add.v4.f32 [%0], {%1,%2,%3,%4};"
                     :: "l"(ap), "f"(m0.x), "f"(m0.y), "f"(m0.z), "f"(m0.w) : "memory");
        asm volatile("red.global.add.v4.f32 [%0], {%1,%2,%3,%4};"
                     :: "l"(ap + 4), "f"(m1.x), "f"(m1.y), "f"(m1.z), "f"(m1.w) : "memory");
    }
}

// ---------------------------------------------------------------------------
// 3-qubit statevector circuit (per node, per thread)
// ---------------------------------------------------------------------------
__device__ __forceinline__ void apply_rx3(float* ar, float* ai, float cb, float sb) {
#pragma unroll
    for (int q = 0; q < 3; q++) {
        int st = 4 >> q;
#pragma unroll
        for (int i = 0; i < 8; i++) {
            if (i & st) continue;
            int j = i + st;
            float a0r = ar[i], a0i = ai[i], a1r = ar[j], a1i = ai[j];
            ar[i] =  cb * a0r + sb * a1i;
            ai[i] =  cb * a0i - sb * a1r;
            ar[j] =  sb * a0i + cb * a1r;
            ai[j] = -sb * a0r + cb * a1i;
        }
    }
}

__device__ __forceinline__ void apply_rz(float* ar, float* ai, int st, float theta) {
    float s, c;
    sincosf(0.5f * theta, &s, &c);
#pragma unroll
    for (int i = 0; i < 8; i++) {
        float r = ar[i], im = ai[i];
        if (i & st) { ar[i] = r * c - im * s; ai[i] = im * c + r * s; }
        else        { ar[i] = r * c + im * s; ai[i] = im * c - r * s; }
    }
}

__device__ __forceinline__ void apply_h(float* ar, float* ai, int st) {
    const float SQ = 0.70710678118654752f;
#pragma unroll
    for (int i = 0; i < 8; i++) {
        if (i & st) continue;
        int j = i + st;
        float a0r = ar[i], a0i = ai[i], a1r = ar[j], a1i = ai[j];
        ar[i] = (a0r + a1r) * SQ; ai[i] = (a0i + a1i) * SQ;
        ar[j] = (a0r - a1r) * SQ; ai[j] = (a0i - a1i) * SQ;
    }
}

__device__ void qcircuit(const float* x, float alpha, float beta, float gamma, float delta,
                         const float* __restrict__ Lam, float* outq)
{
    float ar[8], ai[8];
#pragma unroll
    for (int i = 0; i < 8; i++) { ar[i] = 0.f; ai[i] = 0.f; }
    ar[0] = 1.f;

    // 1) data-encoding RY(alpha * x_q)
#pragma unroll
    for (int q = 0; q < 3; q++) {
        float s, c;
        sincosf(0.5f * alpha * x[q], &s, &c);
        int st = 4 >> q;
#pragma unroll
        for (int i = 0; i < 8; i++) {
            if (i & st) continue;
            int j = i + st;
            float a0r = ar[i], a0i = ai[i], a1r = ar[j], a1i = ai[j];
            ar[i] = c * a0r - s * a1r; ai[i] = c * a0i - s * a1i;
            ar[j] = s * a0r + c * a1r; ai[j] = s * a0i + c * a1i;
        }
    }
    // 2) IsingZZ coupling
#pragma unroll
    for (int qi = 0; qi < 3; qi++)
#pragma unroll
        for (int qj = qi + 1; qj < 3; qj++) {
            float phi = 0.5f * gamma * (Lam[qi * 3 + qj] + Lam[qj * 3 + qi]);
            float sp, cp;
            sincosf(0.5f * phi, &sp, &cp);
#pragma unroll
            for (int i = 0; i < 8; i++) {
                int bi = (i >> (2 - qi)) & 1, bj = (i >> (2 - qj)) & 1;
                float pi = (bi ^ bj) ? sp : -sp;
                float r = ar[i] * cp - ai[i] * pi;
                ai[i]   = ar[i] * pi + ai[i] * cp;
                ar[i]   = r;
            }
        }
    // 3) kinetic RX(beta)
    float sb, cb;
    sincosf(0.5f * beta, &sb, &cb);
    apply_rx3(ar, ai, cb, sb);
    // 4) anharmonic per qubit
#pragma unroll
    for (int q = 0; q < 3; q++) {
        int st = 4 >> q;
        float x2 = x[q] * x[q];
        apply_rz(ar, ai, st, delta * (1.f - 0.5f * x2));
        apply_h(ar, ai, st);
        apply_rz(ar, ai, st, delta * x2);
        apply_h(ar, ai, st);
    }
    // 5) final RX(beta)
    apply_rx3(ar, ai, cb, sb);

    float e0 = 0.f, e1 = 0.f, e2 = 0.f;
#pragma unroll
    for (int i = 0; i < 8; i++) {
        float p = ar[i] * ar[i] + ai[i] * ai[i];
        e0 += (i & 4) ? -p : p;
        e1 += (i & 2) ? -p : p;
        e2 += (i & 1) ? -p : p;
    }
    outq[0] = e0; outq[1] = e1; outq[2] = e2;
}

// ---------------------------------------------------------------------------
// Node kernel: a=[h,agg/100]; q_in = silu(a@qW1+qb1)@qW2+qb2; q_out = circuit;
// out = h + silu([a,q_out]@pW1+pb1)@pW2+pb2.  64 nodes per block.
// ---------------------------------------------------------------------------
#define NODE_SMEM ((64*132 + 131*64 + 64*68) * 4)

__global__ void __launch_bounds__(256, 2) node_kernel(
    const float* __restrict__ h,
    const float* __restrict__ qW1, const float* __restrict__ qb1,
    const float* __restrict__ qW2, const float* __restrict__ qb2,
    const float* __restrict__ pW1, const float* __restrict__ pb1,
    const float* __restrict__ pW2, const float* __restrict__ pb2,
    const float* __restrict__ alpha_p, const float* __restrict__ beta_p,
    const float* __restrict__ gamma_p, const float* __restrict__ delta_p,
    const float* __restrict__ Lam,
    float* __restrict__ out)
{
    extern __shared__ float sm[];
    float* Xs = sm;              // 64 x 132 : [h(64) | agg/100(64) | q_out(3) | pad]
    float* Ws = Xs + 64 * 132;   // up to 131 x 64
    float* Hs = Ws + 131 * 64;   // 64 x 68

    const int tid = threadIdx.x;
    const int nb  = blockIdx.x * 64;

    const float4* h4 = (const float4*)h;
    const float4* a4 = (const float4*)g_agg;
#pragma unroll
    for (int i = 0; i < 8; i++) {
        int f = i * 256 + tid;
        int r = f >> 5, p = f & 31;
        int node = nb + r;
        float4 v = make_float4(0.f, 0.f, 0.f, 0.f);
        if (node < NN) {
            if (p < 16) v = h4[node * 16 + p];
            else {
                v = a4[node * 16 + (p - 16)];
                v.x *= 0.01f; v.y *= 0.01f; v.z *= 0.01f; v.w *= 0.01f;
            }
        }
        ((float4*)Xs)[r * 33 + p] = v;
    }
    if (tid < 64) ((float4*)Xs)[tid * 33 + 32] = make_float4(0.f, 0.f, 0.f, 0.f);

    float4* Ws4 = (float4*)Ws;
#pragma unroll
    for (int i = 0; i < 8; i++) Ws4[i * 256 + tid] = ((const float4*)qW1)[i * 256 + tid];
    __syncthreads();

    const int tx = tid & 15, ty = tid >> 4;
    const int r0 = ty * 4, c0 = tx * 4;
    uint64_t acc[4][2];

    // phase A: H = silu(X[:, :128] @ qW1 + qb1)
#pragma unroll
    for (int i = 0; i < 4; i++) { acc[i][0] = 0ull; acc[i][1] = 0ull; }
#pragma unroll 4
    for (int k = 0; k < 128; k++) {
        ulonglong2 wv = *(const ulonglong2*)&Ws[k * 64 + c0];
#pragma unroll
        for (int i = 0; i < 4; i++) {
            uint64_t xa = dupf(Xs[(r0 + i) * 132 + k]);
            fma2(acc[i][0], xa, wv.x);
            fma2(acc[i][1], xa, wv.y);
        }
    }
    {
        float4 bb = *(const float4*)&qb1[c0];
#pragma unroll
        for (int i = 0; i < 4; i++) {
            float2 p0 = unpk(acc[i][0]), p1 = unpk(acc[i][1]);
            float4 v;
            v.x = silu_f(p0.x + bb.x);
            v.y = silu_f(p0.y + bb.y);
            v.z = silu_f(p1.x + bb.z);
            v.w = silu_f(p1.y + bb.w);
            *(float4*)&Hs[(r0 + i) * 68 + c0] = v;
        }
    }
    __syncthreads();

    // phase B: q_in = H @ qW2 + qb2 ; quantum circuit (one thread per node)
    if (tid < 64) {
        float qin[3] = { qb2[0], qb2[1], qb2[2] };
        for (int k = 0; k < 64; k++) {
            float hv = Hs[tid * 68 + k];
            qin[0] += hv * qW2[k * 3 + 0];
            qin[1] += hv * qW2[k * 3 + 1];
            qin[2] += hv * qW2[k * 3 + 2];
        }
        float qo[3];
        qcircuit(qin, *alpha_p, *beta_p, *gamma_p, *delta_p, Lam, qo);
        Xs[tid * 132 + 128] = qo[0];
        Xs[tid * 132 + 129] = qo[1];
        Xs[tid * 132 + 130] = qo[2];
    }
    __syncthreads();

    // stage pW1 (131x64)
    for (int f = tid; f < 2096; f += 256) Ws4[f] = ((const float4*)pW1)[f];
    __syncthreads();

    // phase C: P = silu(X[:, :131] @ pW1 + pb1)
#pragma unroll
    for (int i = 0; i < 4; i++) { acc[i][0] = 0ull; acc[i][1] = 0ull; }
    for (int k = 0; k < 131; k++) {
        ulonglong2 wv = *(const ulonglong2*)&Ws[k * 64 + c0];
#pragma unroll
        for (int i = 0; i < 4; i++) {
            uint64_t xa = dupf(Xs[(r0 + i) * 132 + k]);
            fma2(acc[i][0], xa, wv.x);
            fma2(acc[i][1], xa, wv.y);
        }
    }
    {
        float4 bb = *(const float4*)&pb1[c0];
#pragma unroll
        for (int i = 0; i < 4; i++) {
            float2 p0 = unpk(acc[i][0]), p1 = unpk(acc[i][1]);
            float4 v;
            v.x = silu_f(p0.x + bb.x);
            v.y = silu_f(p0.y + bb.y);
            v.z = silu_f(p1.x + bb.z);
            v.w = silu_f(p1.y + bb.w);
            *(float4*)&Hs[(r0 + i) * 68 + c0] = v;
        }
    }
    __syncthreads();

    // stage pW2 (64x64)
    for (int f = tid; f < 1024; f += 256) Ws4[f] = ((const float4*)pW2)[f];
    __syncthreads();

    // phase D: out = h + P @ pW2 + pb2
#pragma unroll
    for (int i = 0; i < 4; i++) { acc[i][0] = 0ull; acc[i][1] = 0ull; }
#pragma unroll 4
    for (int k = 0; k < 64; k++) {
        ulonglong2 wv = *(const ulonglong2*)&Ws[k * 64 + c0];
#pragma unroll
        for (int i = 0; i < 4; i++) {
            uint64_t xa = dupf(Hs[(r0 + i) * 68 + k]);
            fma2(acc[i][0], xa, wv.x);
            fma2(acc[i][1], xa, wv.y);
        }
    }
    float4 bb = *(const float4*)&pb2[c0];
#pragma unroll
    for (int i = 0; i < 4; i++) {
        int node = nb + r0 + i;
        if (node < NN) {
            float2 p0 = unpk(acc[i][0]), p1 = unpk(acc[i][1]);
            float4 v;
            v.x = Xs[(r0 + i) * 132 + c0 + 0] + p0.x + bb.x;
            v.y = Xs[(r0 + i) * 132 + c0 + 1] + p0.y + bb.y;
            v.z = Xs[(r0 + i) * 132 + c0 + 2] + p1.x + bb.z;
            v.w = Xs[(r0 + i) * 132 + c0 + 3] + p1.y + bb.w;
            *(float4*)&out[(size_t)node * 64 + c0] = v;
        }
    }
}

// ---------------------------------------------------------------------------
extern "C" void kernel_launch(void* const* d_in, const int* in_sizes, int n_in,
                              void* d_out, int out_size) {
    const float* h   = (const float*)d_in[0];
    const int*   ei  = (const int*)d_in[1];
    const float* eW1 = (const float*)d_in[2];
    const float* eb1 = (const float*)d_in[3];
    const float* eW2 = (const float*)d_in[4];
    const float* eb2 = (const float*)d_in[5];
    const float* qW1 = (const float*)d_in[6];
    const float* qb1 = (const float*)d_in[7];
    const float* qW2 = (const float*)d_in[8];
    const float* qb2 = (const float*)d_in[9];
    const float* pW1 = (const float*)d_in[10];
    const float* pb1 = (const float*)d_in[11];
    const float* pW2 = (const float*)d_in[12];
    const float* pb2 = (const float*)d_in[13];
    const float* al  = (const float*)d_in[14];
    const float* be  = (const float*)d_in[15];
    const float* ga  = (const float*)d_in[16];
    const float* de  = (const float*)d_in[17];
    const float* Lam = (const float*)d_in[18];

    float* out = (float*)d_out;
    float* mij = out + (size_t)NN * DD;

    cudaFuncSetAttribute(edge_kernel, cudaFuncAttributeMaxDynamicSharedMemorySize, EDGE_SMEM);
    cudaFuncSetAttribute(node_kernel, cudaFuncAttributeMaxDynamicSharedMemorySize, NODE_SMEM);

    zero_agg_kernel<<<(NN * DD / 4) / 256, 256>>>();
    edge_kernel<<<NE / 64, 128, EDGE_SMEM>>>(h, ei, ei + NE, eW1, eb1, eW2, eb2, mij);
    node_kernel<<<(NN + 63) / 64, 256, NODE_SMEM>>>(h, qW1, qb1, qW2, qb2,
                                                    pW1, pb1, pW2, pb2,
                                                    al, be, ga, de, Lam, out);
}

// round 11
// speedup vs baseline: 1.5488x; 1.5488x over previous
#include <cuda_runtime.h>
#include <cstdint>

#define NN  50000
#define NE  800000
#define DD  64
#define HID 64

// Scratch: aggregation buffer (allocation-free rule -> __device__ global)
__device__ float g_agg[NN * DD];

__device__ __forceinline__ float silu_f(float v) {
    return v * (1.0f / (1.0f + __expf(-v)));
}

// ---------------- packed f32x2 helpers (Blackwell FFMA2) --------------------
__device__ __forceinline__ uint64_t dupf(float x) {
    uint64_t r; asm("mov.b64 %0, {%1, %1};" : "=l"(r) : "f"(x)); return r;
}
__device__ __forceinline__ void fma2(uint64_t& d, uint64_t a, uint64_t b) {
    asm("fma.rn.f32x2 %0, %1, %2, %0;" : "+l"(d) : "l"(a), "l"(b));
}
__device__ __forceinline__ float2 unpk(uint64_t v) {
    float2 f; asm("mov.b64 {%0, %1}, %2;" : "=f"(f.x), "=f"(f.y) : "l"(v)); return f;
}

// ---------------------------------------------------------------------------
// zero the aggregation scratch (must run every replay)
// ---------------------------------------------------------------------------
__global__ void zero_agg_kernel() {
    int i = blockIdx.x * blockDim.x + threadIdx.x;
    ((float4*)g_agg)[i] = make_float4(0.f, 0.f, 0.f, 0.f);
}

// ---------------------------------------------------------------------------
// Edge kernel: mij = silu(silu([h[row],h[col]]@W1+b1)@W2+b2); agg[row] += mij
// 64 edges per block, 256 threads, 4x4 micro-tiles via packed FFMA2.
// Weight pairs loaded as ulonglong2 (LDS.128 -> aligned reg pairs, no MOVs).
// 16 warps/SM at occ=2 -> 4 warps/SMSP for latency cover.
// ---------------------------------------------------------------------------
#define EDGE_SMEM ((64*128 + 128*64 + 64*64 + 64*68) * 4 + 2 * 64 * 4)

__global__ void __launch_bounds__(256, 2) edge_kernel(
    const float* __restrict__ h, const int* __restrict__ erow, const int* __restrict__ ecol,
    const float* __restrict__ W1, const float* __restrict__ b1,
    const float* __restrict__ W2, const float* __restrict__ b2,
    float* __restrict__ mij)
{
    extern __shared__ float sm[];
    float* Xs  = sm;                     // 64 x 128
    float* W1s = Xs + 64 * 128;          // 128 x 64
    float* W2s = W1s + 128 * 64;         // 64 x 64
    float* Hs  = W2s + 64 * 64;          // 64 x 68 (padded)
    int*   irs = (int*)(Hs + 64 * 68);   // 64 row ids
    int*   ics = irs + 64;               // 64 col ids

    const int tid = threadIdx.x;
    const int eb  = blockIdx.x * 64;

    if (tid < 64)       irs[tid]      = erow[eb + tid];
    else if (tid < 128) ics[tid - 64] = ecol[eb + tid - 64];
    __syncthreads();

    // gather X = [h[row] | h[col]] as float4 (coalesced over 64B chunks)
    const float4* h4 = (const float4*)h;
    float4* X4 = (float4*)Xs;
#pragma unroll
    for (int i = 0; i < 8; i++) {
        int f = i * 256 + tid;
        int r = f >> 5, p = f & 31;
        int node = (p < 16) ? irs[r] : ics[r];
        X4[f] = h4[node * 16 + (p & 15)];
    }
    // stage W1 (2048 float4) and W2 (1024 float4) upfront
#pragma unroll
    for (int i = 0; i < 8; i++)
        ((float4*)W1s)[i * 256 + tid] = ((const float4*)W1)[i * 256 + tid];
#pragma unroll
    for (int i = 0; i < 4; i++)
        ((float4*)W2s)[i * 256 + tid] = ((const float4*)W2)[i * 256 + tid];
    __syncthreads();

    const int tx = tid & 15, ty = tid >> 4;
    const int r0 = ty * 4, c0 = tx * 4;

    // acc[i][j]: row r0+i, column pair (c0+2j, c0+2j+1)
    uint64_t acc[4][2];
#pragma unroll
    for (int i = 0; i < 4; i++) { acc[i][0] = 0ull; acc[i][1] = 0ull; }

    // layer 1: [64x128] @ [128x64]
#pragma unroll 4
    for (int k = 0; k < 128; k++) {
        ulonglong2 wv = *(const ulonglong2*)&W1s[k * 64 + c0];
#pragma unroll
        for (int i = 0; i < 4; i++) {
            uint64_t xa = dupf(Xs[(r0 + i) * 128 + k]);
            fma2(acc[i][0], xa, wv.x);
            fma2(acc[i][1], xa, wv.y);
        }
    }
    {
        float4 bb = *(const float4*)&b1[c0];
#pragma unroll
        for (int i = 0; i < 4; i++) {
            float2 p0 = unpk(acc[i][0]), p1 = unpk(acc[i][1]);
            float4 v;
            v.x = silu_f(p0.x + bb.x);
            v.y = silu_f(p0.y + bb.y);
            v.z = silu_f(p1.x + bb.z);
            v.w = silu_f(p1.y + bb.w);
            *(float4*)&Hs[(r0 + i) * 68 + c0] = v;
        }
    }
    __syncthreads();

#pragma unroll
    for (int i = 0; i < 4; i++) { acc[i][0] = 0ull; acc[i][1] = 0ull; }

    // layer 2: [64x64] @ [64x64]
#pragma unroll 4
    for (int k = 0; k < 64; k++) {
        ulonglong2 wv = *(const ulonglong2*)&W2s[k * 64 + c0];
#pragma unroll
        for (int i = 0; i < 4; i++) {
            uint64_t xa = dupf(Hs[(r0 + i) * 68 + k]);
            fma2(acc[i][0], xa, wv.x);
            fma2(acc[i][1], xa, wv.y);
        }
    }
    float4 b2v = *(const float4*)&b2[c0];
#pragma unroll
    for (int i = 0; i < 4; i++) {
        float2 p0 = unpk(acc[i][0]), p1 = unpk(acc[i][1]);
        float4 m;
        m.x = silu_f(p0.x + b2v.x);
        m.y = silu_f(p0.y + b2v.y);
        m.z = silu_f(p1.x + b2v.z);
        m.w = silu_f(p1.y + b2v.w);
        size_t ge = (size_t)(eb + r0 + i);
        *(float4*)&mij[ge * 64 + c0] = m;
        float* ap = &g_agg[(size_t)irs[r0 + i] * 64 + c0];
        asm volatile("red.global.add.v4.f32 [%0], {%1,%2,%3,%4};"
                     :: "l"(ap), "f"(m.x), "f"(m.y), "f"(m.z), "f"(m.w) : "memory");
    }
}

// ---------------------------------------------------------------------------
// 3-qubit statevector circuit (per node, per thread)
// ---------------------------------------------------------------------------
__device__ __forceinline__ void apply_rx3(float* ar, float* ai, float cb, float sb) {
#pragma unroll
    for (int q = 0; q < 3; q++) {
        int st = 4 >> q;
#pragma unroll
        for (int i = 0; i < 8; i++) {
            if (i & st) continue;
            int j = i + st;
            float a0r = ar[i], a0i = ai[i], a1r = ar[j], a1i = ai[j];
            ar[i] =  cb * a0r + sb * a1i;
            ai[i] =  cb * a0i - sb * a1r;
            ar[j] =  sb * a0i + cb * a1r;
            ai[j] = -sb * a0r + cb * a1i;
        }
    }
}

__device__ __forceinline__ void apply_rz(float* ar, float* ai, int st, float theta) {
    float s, c;
    sincosf(0.5f * theta, &s, &c);
#pragma unroll
    for (int i = 0; i < 8; i++) {
        float r = ar[i], im = ai[i];
        if (i & st) { ar[i] = r * c - im * s; ai[i] = im * c + r * s; }
        else        { ar[i] = r * c + im * s; ai[i] = im * c - r * s; }
    }
}

__device__ __forceinline__ void apply_h(float* ar, float* ai, int st) {
    const float SQ = 0.70710678118654752f;
#pragma unroll
    for (int i = 0; i < 8; i++) {
        if (i & st) continue;
        int j = i + st;
        float a0r = ar[i], a0i = ai[i], a1r = ar[j], a1i = ai[j];
        ar[i] = (a0r + a1r) * SQ; ai[i] = (a0i + a1i) * SQ;
        ar[j] = (a0r - a1r) * SQ; ai[j] = (a0i - a1i) * SQ;
    }
}

__device__ void qcircuit(const float* x, float alpha, float beta, float gamma, float delta,
                         const float* __restrict__ Lam, float* outq)
{
    float ar[8], ai[8];
#pragma unroll
    for (int i = 0; i < 8; i++) { ar[i] = 0.f; ai[i] = 0.f; }
    ar[0] = 1.f;

    // 1) data-encoding RY(alpha * x_q)
#pragma unroll
    for (int q = 0; q < 3; q++) {
        float s, c;
        sincosf(0.5f * alpha * x[q], &s, &c);
        int st = 4 >> q;
#pragma unroll
        for (int i = 0; i < 8; i++) {
            if (i & st) continue;
            int j = i + st;
            float a0r = ar[i], a0i = ai[i], a1r = ar[j], a1i = ai[j];
            ar[i] = c * a0r - s * a1r; ai[i] = c * a0i - s * a1i;
            ar[j] = s * a0r + c * a1r; ai[j] = s * a0i + c * a1i;
        }
    }
    // 2) IsingZZ coupling
#pragma unroll
    for (int qi = 0; qi < 3; qi++)
#pragma unroll
        for (int qj = qi + 1; qj < 3; qj++) {
            float phi = 0.5f * gamma * (Lam[qi * 3 + qj] + Lam[qj * 3 + qi]);
            float sp, cp;
            sincosf(0.5f * phi, &sp, &cp);
#pragma unroll
            for (int i = 0; i < 8; i++) {
                int bi = (i >> (2 - qi)) & 1, bj = (i >> (2 - qj)) & 1;
                float pi = (bi ^ bj) ? sp : -sp;
                float r = ar[i] * cp - ai[i] * pi;
                ai[i]   = ar[i] * pi + ai[i] * cp;
                ar[i]   = r;
            }
        }
    // 3) kinetic RX(beta)
    float sb, cb;
    sincosf(0.5f * beta, &sb, &cb);
    apply_rx3(ar, ai, cb, sb);
    // 4) anharmonic per qubit
#pragma unroll
    for (int q = 0; q < 3; q++) {
        int st = 4 >> q;
        float x2 = x[q] * x[q];
        apply_rz(ar, ai, st, delta * (1.f - 0.5f * x2));
        apply_h(ar, ai, st);
        apply_rz(ar, ai, st, delta * x2);
        apply_h(ar, ai, st);
    }
    // 5) final RX(beta)
    apply_rx3(ar, ai, cb, sb);

    float e0 = 0.f, e1 = 0.f, e2 = 0.f;
#pragma unroll
    for (int i = 0; i < 8; i++) {
        float p = ar[i] * ar[i] + ai[i] * ai[i];
        e0 += (i & 4) ? -p : p;
        e1 += (i & 2) ? -p : p;
        e2 += (i & 1) ? -p : p;
    }
    outq[0] = e0; outq[1] = e1; outq[2] = e2;
}

// ---------------------------------------------------------------------------
// Node kernel: a=[h,agg/100]; q_in = silu(a@qW1+qb1)@qW2+qb2; q_out = circuit;
// out = h + silu([a,q_out]@pW1+pb1)@pW2+pb2.  64 nodes per block.
// ---------------------------------------------------------------------------
#define NODE_SMEM ((64*132 + 131*64 + 64*68) * 4)

__global__ void __launch_bounds__(256, 2) node_kernel(
    const float* __restrict__ h,
    const float* __restrict__ qW1, const float* __restrict__ qb1,
    const float* __restrict__ qW2, const float* __restrict__ qb2,
    const float* __restrict__ pW1, const float* __restrict__ pb1,
    const float* __restrict__ pW2, const float* __restrict__ pb2,
    const float* __restrict__ alpha_p, const float* __restrict__ beta_p,
    const float* __restrict__ gamma_p, const float* __restrict__ delta_p,
    const float* __restrict__ Lam,
    float* __restrict__ out)
{
    extern __shared__ float sm[];
    float* Xs = sm;              // 64 x 132 : [h(64) | agg/100(64) | q_out(3) | pad]
    float* Ws = Xs + 64 * 132;   // up to 131 x 64
    float* Hs = Ws + 131 * 64;   // 64 x 68

    const int tid = threadIdx.x;
    const int nb  = blockIdx.x * 64;

    const float4* h4 = (const float4*)h;
    const float4* a4 = (const float4*)g_agg;
#pragma unroll
    for (int i = 0; i < 8; i++) {
        int f = i * 256 + tid;
        int r = f >> 5, p = f & 31;
        int node = nb + r;
        float4 v = make_float4(0.f, 0.f, 0.f, 0.f);
        if (node < NN) {
            if (p < 16) v = h4[node * 16 + p];
            else {
                v = a4[node * 16 + (p - 16)];
                v.x *= 0.01f; v.y *= 0.01f; v.z *= 0.01f; v.w *= 0.01f;
            }
        }
        ((float4*)Xs)[r * 33 + p] = v;
    }
    if (tid < 64) ((float4*)Xs)[tid * 33 + 32] = make_float4(0.f, 0.f, 0.f, 0.f);

    float4* Ws4 = (float4*)Ws;
#pragma unroll
    for (int i = 0; i < 8; i++) Ws4[i * 256 + tid] = ((const float4*)qW1)[i * 256 + tid];
    __syncthreads();

    const int tx = tid & 15, ty = tid >> 4;
    const int r0 = ty * 4, c0 = tx * 4;
    uint64_t acc[4][2];

    // phase A: H = silu(X[:, :128] @ qW1 + qb1)
#pragma unroll
    for (int i = 0; i < 4; i++) { acc[i][0] = 0ull; acc[i][1] = 0ull; }
#pragma unroll 4
    for (int k = 0; k < 128; k++) {
        ulonglong2 wv = *(const ulonglong2*)&Ws[k * 64 + c0];
#pragma unroll
        for (int i = 0; i < 4; i++) {
            uint64_t xa = dupf(Xs[(r0 + i) * 132 + k]);
            fma2(acc[i][0], xa, wv.x);
            fma2(acc[i][1], xa, wv.y);
        }
    }
    {
        float4 bb = *(const float4*)&qb1[c0];
#pragma unroll
        for (int i = 0; i < 4; i++) {
            float2 p0 = unpk(acc[i][0]), p1 = unpk(acc[i][1]);
            float4 v;
            v.x = silu_f(p0.x + bb.x);
            v.y = silu_f(p0.y + bb.y);
            v.z = silu_f(p1.x + bb.z);
            v.w = silu_f(p1.y + bb.w);
            *(float4*)&Hs[(r0 + i) * 68 + c0] = v;
        }
    }
    __syncthreads();

    // phase B: q_in = H @ qW2 + qb2 ; quantum circuit (one thread per node)
    if (tid < 64) {
        float qin[3] = { qb2[0], qb2[1], qb2[2] };
        for (int k = 0; k < 64; k++) {
            float hv = Hs[tid * 68 + k];
            qin[0] += hv * qW2[k * 3 + 0];
            qin[1] += hv * qW2[k * 3 + 1];
            qin[2] += hv * qW2[k * 3 + 2];
        }
        float qo[3];
        qcircuit(qin, *alpha_p, *beta_p, *gamma_p, *delta_p, Lam, qo);
        Xs[tid * 132 + 128] = qo[0];
        Xs[tid * 132 + 129] = qo[1];
        Xs[tid * 132 + 130] = qo[2];
    }
    __syncthreads();

    // stage pW1 (131x64)
    for (int f = tid; f < 2096; f += 256) Ws4[f] = ((const float4*)pW1)[f];
    __syncthreads();

    // phase C: P = silu(X[:, :131] @ pW1 + pb1)
#pragma unroll
    for (int i = 0; i < 4; i++) { acc[i][0] = 0ull; acc[i][1] = 0ull; }
    for (int k = 0; k < 131; k++) {
        ulonglong2 wv = *(const ulonglong2*)&Ws[k * 64 + c0];
#pragma unroll
        for (int i = 0; i < 4; i++) {
            uint64_t xa = dupf(Xs[(r0 + i) * 132 + k]);
            fma2(acc[i][0], xa, wv.x);
            fma2(acc[i][1], xa, wv.y);
        }
    }
    {
        float4 bb = *(const float4*)&pb1[c0];
#pragma unroll
        for (int i = 0; i < 4; i++) {
            float2 p0 = unpk(acc[i][0]), p1 = unpk(acc[i][1]);
            float4 v;
            v.x = silu_f(p0.x + bb.x);
            v.y = silu_f(p0.y + bb.y);
            v.z = silu_f(p1.x + bb.z);
            v.w = silu_f(p1.y + bb.w);
            *(float4*)&Hs[(r0 + i) * 68 + c0] = v;
        }
    }
    __syncthreads();

    // stage pW2 (64x64)
    for (int f = tid; f < 1024; f += 256) Ws4[f] = ((const float4*)pW2)[f];
    __syncthreads();

    // phase D: out = h + P @ pW2 + pb2
#pragma unroll
    for (int i = 0; i < 4; i++) { acc[i][0] = 0ull; acc[i][1] = 0ull; }
#pragma unroll 4
    for (int k = 0; k < 64; k++) {
        ulonglong2 wv = *(const ulonglong2*)&Ws[k * 64 + c0];
#pragma unroll
        for (int i = 0; i < 4; i++) {
            uint64_t xa = dupf(Hs[(r0 + i) * 68 + k]);
            fma2(acc[i][0], xa, wv.x);
            fma2(acc[i][1], xa, wv.y);
        }
    }
    float4 bb = *(const float4*)&pb2[c0];
#pragma unroll
    for (int i = 0; i < 4; i++) {
        int node = nb + r0 + i;
        if (node < NN) {
            float2 p0 = unpk(acc[i][0]), p1 = unpk(acc[i][1]);
            float4 v;
            v.x = Xs[(r0 + i) * 132 + c0 + 0] + p0.x + bb.x;
            v.y = Xs[(r0 + i) * 132 + c0 + 1] + p0.y + bb.y;
            v.z = Xs[(r0 + i) * 132 + c0 + 2] + p1.x + bb.z;
            v.w = Xs[(r0 + i) * 132 + c0 + 3] + p1.y + bb.w;
            *(float4*)&out[(size_t)node * 64 + c0] = v;
        }
    }
}

// ---------------------------------------------------------------------------
extern "C" void kernel_launch(void* const* d_in, const int* in_sizes, int n_in,
                              void* d_out, int out_size) {
    const float* h   = (const float*)d_in[0];
    const int*   ei  = (const int*)d_in[1];
    const float* eW1 = (const float*)d_in[2];
    const float* eb1 = (const float*)d_in[3];
    const float* eW2 = (const float*)d_in[4];
    const float* eb2 = (const float*)d_in[5];
    const float* qW1 = (const float*)d_in[6];
    const float* qb1 = (const float*)d_in[7];
    const float* qW2 = (const float*)d_in[8];
    const float* qb2 = (const float*)d_in[9];
    const float* pW1 = (const float*)d_in[10];
    const float* pb1 = (const float*)d_in[11];
    const float* pW2 = (const float*)d_in[12];
    const float* pb2 = (const float*)d_in[13];
    const float* al  = (const float*)d_in[14];
    const float* be  = (const float*)d_in[15];
    const float* ga  = (const float*)d_in[16];
    const float* de  = (const float*)d_in[17];
    const float* Lam = (const float*)d_in[18];

    float* out = (float*)d_out;
    float* mij = out + (size_t)NN * DD;

    cudaFuncSetAttribute(edge_kernel, cudaFuncAttributeMaxDynamicSharedMemorySize, EDGE_SMEM);
    cudaFuncSetAttribute(node_kernel, cudaFuncAttributeMaxDynamicSharedMemorySize, NODE_SMEM);

    zero_agg_kernel<<<(NN * DD / 4) / 256, 256>>>();
    edge_kernel<<<NE / 64, 256, EDGE_SMEM>>>(h, ei, ei + NE, eW1, eb1, eW2, eb2, mij);
    node_kernel<<<(NN + 63) / 64, 256, NODE_SMEM>>>(h, qW1, qb1, qW2, qb2,
                                                    pW1, pb1, pW2, pb2,
                                                    al, be, ga, de, Lam, out);
}

// round 12
// speedup vs baseline: 1.5749x; 1.0169x over previous
#include <cuda_runtime.h>
#include <cstdint>

#define NN  50000
#define NE  800000
#define DD  64
#define HID 64

// Scratch: aggregation buffer (allocation-free rule -> __device__ global)
__device__ float g_agg[NN * DD];

__device__ __forceinline__ float silu_f(float v) {
    return v * (1.0f / (1.0f + __expf(-v)));
}

// ---------------- packed f32x2 helpers (Blackwell FFMA2) --------------------
__device__ __forceinline__ uint64_t dupf(float x) {
    uint64_t r; asm("mov.b64 %0, {%1, %1};" : "=l"(r) : "f"(x)); return r;
}
__device__ __forceinline__ void fma2(uint64_t& d, uint64_t a, uint64_t b) {
    asm("fma.rn.f32x2 %0, %1, %2, %0;" : "+l"(d) : "l"(a), "l"(b));
}
__device__ __forceinline__ float2 unpk(uint64_t v) {
    float2 f; asm("mov.b64 {%0, %1}, %2;" : "=f"(f.x), "=f"(f.y) : "l"(v)); return f;
}

// one k-step of the 4-row x 4-col micro-tile: dup x once, 2 FFMA2 per row
#define MICRO_K(acc, xv, wv)                                     \
    do {                                                         \
        uint64_t _dx = dupf(xv);                                 \
        fma2((acc)[0], _dx, (wv).x);                             \
        fma2((acc)[1], _dx, (wv).y);                             \
    } while (0)

// ---------------------------------------------------------------------------
// zero the aggregation scratch (must run every replay)
// ---------------------------------------------------------------------------
__global__ void zero_agg_kernel() {
    int i = blockIdx.x * blockDim.x + threadIdx.x;
    ((float4*)g_agg)[i] = make_float4(0.f, 0.f, 0.f, 0.f);
}

// ---------------------------------------------------------------------------
// Edge kernel: mij = silu(silu([h[row],h[col]]@W1+b1)@W2+b2); agg[row] += mij
// 64 edges per block, 256 threads, 4x4 micro-tiles via packed FFMA2.
// k-blocked by 4: x loaded via LDS.128 (1 crossbar cyc, broadcast) per 4 MACs
// -> smem crossbar 48 SM-cyc/k (was 96), FFMA2-pipe-bound.
// ---------------------------------------------------------------------------
#define EDGE_SMEM ((64*128 + 128*64 + 64*64 + 64*68) * 4 + 2 * 64 * 4)

__global__ void __launch_bounds__(256, 2) edge_kernel(
    const float* __restrict__ h, const int* __restrict__ erow, const int* __restrict__ ecol,
    const float* __restrict__ W1, const float* __restrict__ b1,
    const float* __restrict__ W2, const float* __restrict__ b2,
    float* __restrict__ mij)
{
    extern __shared__ float sm[];
    float* Xs  = sm;                     // 64 x 128
    float* W1s = Xs + 64 * 128;          // 128 x 64
    float* W2s = W1s + 128 * 64;         // 64 x 64
    float* Hs  = W2s + 64 * 64;          // 64 x 68 (padded)
    int*   irs = (int*)(Hs + 64 * 68);   // 64 row ids
    int*   ics = irs + 64;               // 64 col ids

    const int tid = threadIdx.x;
    const int eb  = blockIdx.x * 64;

    if (tid < 64)       irs[tid]      = erow[eb + tid];
    else if (tid < 128) ics[tid - 64] = ecol[eb + tid - 64];
    __syncthreads();

    // gather X = [h[row] | h[col]] as float4 (coalesced over 64B chunks)
    const float4* h4 = (const float4*)h;
    float4* X4 = (float4*)Xs;
#pragma unroll
    for (int i = 0; i < 8; i++) {
        int f = i * 256 + tid;
        int r = f >> 5, p = f & 31;
        int node = (p < 16) ? irs[r] : ics[r];
        X4[f] = h4[node * 16 + (p & 15)];
    }
    // stage W1 (2048 float4) and W2 (1024 float4) upfront
#pragma unroll
    for (int i = 0; i < 8; i++)
        ((float4*)W1s)[i * 256 + tid] = ((const float4*)W1)[i * 256 + tid];
#pragma unroll
    for (int i = 0; i < 4; i++)
        ((float4*)W2s)[i * 256 + tid] = ((const float4*)W2)[i * 256 + tid];
    __syncthreads();

    const int tx = tid & 15, ty = tid >> 4;
    const int r0 = ty * 4, c0 = tx * 4;

    // acc[i][j]: row r0+i, column pair (c0+2j, c0+2j+1)
    uint64_t acc[4][2];
#pragma unroll
    for (int i = 0; i < 4; i++) { acc[i][0] = 0ull; acc[i][1] = 0ull; }

    // layer 1: [64x128] @ [128x64], k-blocked by 4
#pragma unroll 2
    for (int k4 = 0; k4 < 128; k4 += 4) {
        ulonglong2 w0 = *(const ulonglong2*)&W1s[(k4 + 0) * 64 + c0];
        ulonglong2 w1 = *(const ulonglong2*)&W1s[(k4 + 1) * 64 + c0];
        ulonglong2 w2 = *(const ulonglong2*)&W1s[(k4 + 2) * 64 + c0];
        ulonglong2 w3 = *(const ulonglong2*)&W1s[(k4 + 3) * 64 + c0];
#pragma unroll
        for (int i = 0; i < 4; i++) {
            float4 xv = *(const float4*)&Xs[(r0 + i) * 128 + k4];
            MICRO_K(acc[i], xv.x, w0);
            MICRO_K(acc[i], xv.y, w1);
            MICRO_K(acc[i], xv.z, w2);
            MICRO_K(acc[i], xv.w, w3);
        }
    }
    {
        float4 bb = *(const float4*)&b1[c0];
#pragma unroll
        for (int i = 0; i < 4; i++) {
            float2 p0 = unpk(acc[i][0]), p1 = unpk(acc[i][1]);
            float4 v;
            v.x = silu_f(p0.x + bb.x);
            v.y = silu_f(p0.y + bb.y);
            v.z = silu_f(p1.x + bb.z);
            v.w = silu_f(p1.y + bb.w);
            *(float4*)&Hs[(r0 + i) * 68 + c0] = v;
        }
    }
    __syncthreads();

#pragma unroll
    for (int i = 0; i < 4; i++) { acc[i][0] = 0ull; acc[i][1] = 0ull; }

    // layer 2: [64x64] @ [64x64], k-blocked by 4
#pragma unroll 2
    for (int k4 = 0; k4 < 64; k4 += 4) {
        ulonglong2 w0 = *(const ulonglong2*)&W2s[(k4 + 0) * 64 + c0];
        ulonglong2 w1 = *(const ulonglong2*)&W2s[(k4 + 1) * 64 + c0];
        ulonglong2 w2 = *(const ulonglong2*)&W2s[(k4 + 2) * 64 + c0];
        ulonglong2 w3 = *(const ulonglong2*)&W2s[(k4 + 3) * 64 + c0];
#pragma unroll
        for (int i = 0; i < 4; i++) {
            float4 xv = *(const float4*)&Hs[(r0 + i) * 68 + k4];
            MICRO_K(acc[i], xv.x, w0);
            MICRO_K(acc[i], xv.y, w1);
            MICRO_K(acc[i], xv.z, w2);
            MICRO_K(acc[i], xv.w, w3);
        }
    }
    float4 b2v = *(const float4*)&b2[c0];
#pragma unroll
    for (int i = 0; i < 4; i++) {
        float2 p0 = unpk(acc[i][0]), p1 = unpk(acc[i][1]);
        float4 m;
        m.x = silu_f(p0.x + b2v.x);
        m.y = silu_f(p0.y + b2v.y);
        m.z = silu_f(p1.x + b2v.z);
        m.w = silu_f(p1.y + b2v.w);
        size_t ge = (size_t)(eb + r0 + i);
        *(float4*)&mij[ge * 64 + c0] = m;
        float* ap = &g_agg[(size_t)irs[r0 + i] * 64 + c0];
        asm volatile("red.global.add.v4.f32 [%0], {%1,%2,%3,%4};"
                     :: "l"(ap), "f"(m.x), "f"(m.y), "f"(m.z), "f"(m.w) : "memory");
    }
}

// ---------------------------------------------------------------------------
// 3-qubit statevector circuit (per node, per thread)
// ---------------------------------------------------------------------------
__device__ __forceinline__ void apply_rx3(float* ar, float* ai, float cb, float sb) {
#pragma unroll
    for (int q = 0; q < 3; q++) {
        int st = 4 >> q;
#pragma unroll
        for (int i = 0; i < 8; i++) {
            if (i & st) continue;
            int j = i + st;
            float a0r = ar[i], a0i = ai[i], a1r = ar[j], a1i = ai[j];
            ar[i] =  cb * a0r + sb * a1i;
            ai[i] =  cb * a0i - sb * a1r;
            ar[j] =  sb * a0i + cb * a1r;
            ai[j] = -sb * a0r + cb * a1i;
        }
    }
}

__device__ __forceinline__ void apply_rz(float* ar, float* ai, int st, float theta) {
    float s, c;
    sincosf(0.5f * theta, &s, &c);
#pragma unroll
    for (int i = 0; i < 8; i++) {
        float r = ar[i], im = ai[i];
        if (i & st) { ar[i] = r * c - im * s; ai[i] = im * c + r * s; }
        else        { ar[i] = r * c + im * s; ai[i] = im * c - r * s; }
    }
}

__device__ __forceinline__ void apply_h(float* ar, float* ai, int st) {
    const float SQ = 0.70710678118654752f;
#pragma unroll
    for (int i = 0; i < 8; i++) {
        if (i & st) continue;
        int j = i + st;
        float a0r = ar[i], a0i = ai[i], a1r = ar[j], a1i = ai[j];
        ar[i] = (a0r + a1r) * SQ; ai[i] = (a0i + a1i) * SQ;
        ar[j] = (a0r - a1r) * SQ; ai[j] = (a0i - a1i) * SQ;
    }
}

__device__ void qcircuit(const float* x, float alpha, float beta, float gamma, float delta,
                         const float* __restrict__ Lam, float* outq)
{
    float ar[8], ai[8];
#pragma unroll
    for (int i = 0; i < 8; i++) { ar[i] = 0.f; ai[i] = 0.f; }
    ar[0] = 1.f;

    // 1) data-encoding RY(alpha * x_q)
#pragma unroll
    for (int q = 0; q < 3; q++) {
        float s, c;
        sincosf(0.5f * alpha * x[q], &s, &c);
        int st = 4 >> q;
#pragma unroll
        for (int i = 0; i < 8; i++) {
            if (i & st) continue;
            int j = i + st;
            float a0r = ar[i], a0i = ai[i], a1r = ar[j], a1i = ai[j];
            ar[i] = c * a0r - s * a1r; ai[i] = c * a0i - s * a1i;
            ar[j] = s * a0r + c * a1r; ai[j] = s * a0i + c * a1i;
        }
    }
    // 2) IsingZZ coupling
#pragma unroll
    for (int qi = 0; qi < 3; qi++)
#pragma unroll
        for (int qj = qi + 1; qj < 3; qj++) {
            float phi = 0.5f * gamma * (Lam[qi * 3 + qj] + Lam[qj * 3 + qi]);
            float sp, cp;
            sincosf(0.5f * phi, &sp, &cp);
#pragma unroll
            for (int i = 0; i < 8; i++) {
                int bi = (i >> (2 - qi)) & 1, bj = (i >> (2 - qj)) & 1;
                float pi = (bi ^ bj) ? sp : -sp;
                float r = ar[i] * cp - ai[i] * pi;
                ai[i]   = ar[i] * pi + ai[i] * cp;
                ar[i]   = r;
            }
        }
    // 3) kinetic RX(beta)
    float sb, cb;
    sincosf(0.5f * beta, &sb, &cb);
    apply_rx3(ar, ai, cb, sb);
    // 4) anharmonic per qubit
#pragma unroll
    for (int q = 0; q < 3; q++) {
        int st = 4 >> q;
        float x2 = x[q] * x[q];
        apply_rz(ar, ai, st, delta * (1.f - 0.5f * x2));
        apply_h(ar, ai, st);
        apply_rz(ar, ai, st, delta * x2);
        apply_h(ar, ai, st);
    }
    // 5) final RX(beta)
    apply_rx3(ar, ai, cb, sb);

    float e0 = 0.f, e1 = 0.f, e2 = 0.f;
#pragma unroll
    for (int i = 0; i < 8; i++) {
        float p = ar[i] * ar[i] + ai[i] * ai[i];
        e0 += (i & 4) ? -p : p;
        e1 += (i & 2) ? -p : p;
        e2 += (i & 1) ? -p : p;
    }
    outq[0] = e0; outq[1] = e1; outq[2] = e2;
}

// ---------------------------------------------------------------------------
// Node kernel: a=[h,agg/100]; q_in = silu(a@qW1+qb1)@qW2+qb2; q_out = circuit;
// out = h + silu([a,q_out]@pW1+pb1)@pW2+pb2.  64 nodes per block.
// ---------------------------------------------------------------------------
#define NODE_SMEM ((64*132 + 131*64 + 64*68) * 4)

__global__ void __launch_bounds__(256, 2) node_kernel(
    const float* __restrict__ h,
    const float* __restrict__ qW1, const float* __restrict__ qb1,
    const float* __restrict__ qW2, const float* __restrict__ qb2,
    const float* __restrict__ pW1, const float* __restrict__ pb1,
    const float* __restrict__ pW2, const float* __restrict__ pb2,
    const float* __restrict__ alpha_p, const float* __restrict__ beta_p,
    const float* __restrict__ gamma_p, const float* __restrict__ delta_p,
    const float* __restrict__ Lam,
    float* __restrict__ out)
{
    extern __shared__ float sm[];
    float* Xs = sm;              // 64 x 132 : [h(64) | agg/100(64) | q_out(3) | pad]
    float* Ws = Xs + 64 * 132;   // up to 131 x 64
    float* Hs = Ws + 131 * 64;   // 64 x 68

    const int tid = threadIdx.x;
    const int nb  = blockIdx.x * 64;

    const float4* h4 = (const float4*)h;
    const float4* a4 = (const float4*)g_agg;
#pragma unroll
    for (int i = 0; i < 8; i++) {
        int f = i * 256 + tid;
        int r = f >> 5, p = f & 31;
        int node = nb + r;
        float4 v = make_float4(0.f, 0.f, 0.f, 0.f);
        if (node < NN) {
            if (p < 16) v = h4[node * 16 + p];
            else {
                v = a4[node * 16 + (p - 16)];
                v.x *= 0.01f; v.y *= 0.01f; v.z *= 0.01f; v.w *= 0.01f;
            }
        }
        ((float4*)Xs)[r * 33 + p] = v;
    }
    if (tid < 64) ((float4*)Xs)[tid * 33 + 32] = make_float4(0.f, 0.f, 0.f, 0.f);

    float4* Ws4 = (float4*)Ws;
#pragma unroll
    for (int i = 0; i < 8; i++) Ws4[i * 256 + tid] = ((const float4*)qW1)[i * 256 + tid];
    __syncthreads();

    const int tx = tid & 15, ty = tid >> 4;
    const int r0 = ty * 4, c0 = tx * 4;
    uint64_t acc[4][2];

    // phase A: H = silu(X[:, :128] @ qW1 + qb1), k-blocked by 4
#pragma unroll
    for (int i = 0; i < 4; i++) { acc[i][0] = 0ull; acc[i][1] = 0ull; }
#pragma unroll 2
    for (int k4 = 0; k4 < 128; k4 += 4) {
        ulonglong2 w0 = *(const ulonglong2*)&Ws[(k4 + 0) * 64 + c0];
        ulonglong2 w1 = *(const ulonglong2*)&Ws[(k4 + 1) * 64 + c0];
        ulonglong2 w2 = *(const ulonglong2*)&Ws[(k4 + 2) * 64 + c0];
        ulonglong2 w3 = *(const ulonglong2*)&Ws[(k4 + 3) * 64 + c0];
#pragma unroll
        for (int i = 0; i < 4; i++) {
            float4 xv = *(const float4*)&Xs[(r0 + i) * 132 + k4];
            MICRO_K(acc[i], xv.x, w0);
            MICRO_K(acc[i], xv.y, w1);
            MICRO_K(acc[i], xv.z, w2);
            MICRO_K(acc[i], xv.w, w3);
        }
    }
    {
        float4 bb = *(const float4*)&qb1[c0];
#pragma unroll
        for (int i = 0; i < 4; i++) {
            float2 p0 = unpk(acc[i][0]), p1 = unpk(acc[i][1]);
            float4 v;
            v.x = silu_f(p0.x + bb.x);
            v.y = silu_f(p0.y + bb.y);
            v.z = silu_f(p1.x + bb.z);
            v.w = silu_f(p1.y + bb.w);
            *(float4*)&Hs[(r0 + i) * 68 + c0] = v;
        }
    }
    __syncthreads();

    // phase B: q_in = H @ qW2 + qb2 ; quantum circuit (one thread per node)
    if (tid < 64) {
        float qin[3] = { qb2[0], qb2[1], qb2[2] };
        for (int k = 0; k < 64; k++) {
            float hv = Hs[tid * 68 + k];
            qin[0] += hv * qW2[k * 3 + 0];
            qin[1] += hv * qW2[k * 3 + 1];
            qin[2] += hv * qW2[k * 3 + 2];
        }
        float qo[3];
        qcircuit(qin, *alpha_p, *beta_p, *gamma_p, *delta_p, Lam, qo);
        Xs[tid * 132 + 128] = qo[0];
        Xs[tid * 132 + 129] = qo[1];
        Xs[tid * 132 + 130] = qo[2];
    }
    __syncthreads();

    // stage pW1 (131x64)
    for (int f = tid; f < 2096; f += 256) Ws4[f] = ((const float4*)pW1)[f];
    __syncthreads();

    // phase C: P = silu(X[:, :131] @ pW1 + pb1), k-blocked by 4 + 3-tail
#pragma unroll
    for (int i = 0; i < 4; i++) { acc[i][0] = 0ull; acc[i][1] = 0ull; }
#pragma unroll 2
    for (int k4 = 0; k4 < 128; k4 += 4) {
        ulonglong2 w0 = *(const ulonglong2*)&Ws[(k4 + 0) * 64 + c0];
        ulonglong2 w1 = *(const ulonglong2*)&Ws[(k4 + 1) * 64 + c0];
        ulonglong2 w2 = *(const ulonglong2*)&Ws[(k4 + 2) * 64 + c0];
        ulonglong2 w3 = *(const ulonglong2*)&Ws[(k4 + 3) * 64 + c0];
#pragma unroll
        for (int i = 0; i < 4; i++) {
            float4 xv = *(const float4*)&Xs[(r0 + i) * 132 + k4];
            MICRO_K(acc[i], xv.x, w0);
            MICRO_K(acc[i], xv.y, w1);
            MICRO_K(acc[i], xv.z, w2);
            MICRO_K(acc[i], xv.w, w3);
        }
    }
#pragma unroll
    for (int k = 128; k < 131; k++) {
        ulonglong2 wv = *(const ulonglong2*)&Ws[k * 64 + c0];
#pragma unroll
        for (int i = 0; i < 4; i++) {
            MICRO_K(acc[i], Xs[(r0 + i) * 132 + k], wv);
        }
    }
    {
        float4 bb = *(const float4*)&pb1[c0];
#pragma unroll
        for (int i = 0; i < 4; i++) {
            float2 p0 = unpk(acc[i][0]), p1 = unpk(acc[i][1]);
            float4 v;
            v.x = silu_f(p0.x + bb.x);
            v.y = silu_f(p0.y + bb.y);
            v.z = silu_f(p1.x + bb.z);
            v.w = silu_f(p1.y + bb.w);
            *(float4*)&Hs[(r0 + i) * 68 + c0] = v;
        }
    }
    __syncthreads();

    // stage pW2 (64x64)
    for (int f = tid; f < 1024; f += 256) Ws4[f] = ((const float4*)pW2)[f];
    __syncthreads();

    // phase D: out = h + P @ pW2 + pb2, k-blocked by 4
#pragma unroll
    for (int i = 0; i < 4; i++) { acc[i][0] = 0ull; acc[i][1] = 0ull; }
#pragma unroll 2
    for (int k4 = 0; k4 < 64; k4 += 4) {
        ulonglong2 w0 = *(const ulonglong2*)&Ws[(k4 + 0) * 64 + c0];
        ulonglong2 w1 = *(const ulonglong2*)&Ws[(k4 + 1) * 64 + c0];
        ulonglong2 w2 = *(const ulonglong2*)&Ws[(k4 + 2) * 64 + c0];
        ulonglong2 w3 = *(const ulonglong2*)&Ws[(k4 + 3) * 64 + c0];
#pragma unroll
        for (int i = 0; i < 4; i++) {
            float4 xv = *(const float4*)&Hs[(r0 + i) * 68 + k4];
            MICRO_K(acc[i], xv.x, w0);
            MICRO_K(acc[i], xv.y, w1);
            MICRO_K(acc[i], xv.z, w2);
            MICRO_K(acc[i], xv.w, w3);
        }
    }
    float4 bb = *(const float4*)&pb2[c0];
#pragma unroll
    for (int i = 0; i < 4; i++) {
        int node = nb + r0 + i;
        if (node < NN) {
            float2 p0 = unpk(acc[i][0]), p1 = unpk(acc[i][1]);
            float4 v;
            v.x = Xs[(r0 + i) * 132 + c0 + 0] + p0.x + bb.x;
            v.y = Xs[(r0 + i) * 132 + c0 + 1] + p0.y + bb.y;
            v.z = Xs[(r0 + i) * 132 + c0 + 2] + p1.x + bb.z;
            v.w = Xs[(r0 + i) * 132 + c0 + 3] + p1.y + bb.w;
            *(float4*)&out[(size_t)node * 64 + c0] = v;
        }
    }
}

// ---------------------------------------------------------------------------
extern "C" void kernel_launch(void* const* d_in, const int* in_sizes, int n_in,
                              void* d_out, int out_size) {
    const float* h   = (const float*)d_in[0];
    const int*   ei  = (const int*)d_in[1];
    const float* eW1 = (const float*)d_in[2];
    const float* eb1 = (const float*)d_in[3];
    const float* eW2 = (const float*)d_in[4];
    const float* eb2 = (const float*)d_in[5];
    const float* qW1 = (const float*)d_in[6];
    const float* qb1 = (const float*)d_in[7];
    const float* qW2 = (const float*)d_in[8];
    const float* qb2 = (const float*)d_in[9];
    const float* pW1 = (const float*)d_in[10];
    const float* pb1 = (const float*)d_in[11];
    const float* pW2 = (const float*)d_in[12];
    const float* pb2 = (const float*)d_in[13];
    const float* al  = (const float*)d_in[14];
    const float* be  = (const float*)d_in[15];
    const float* ga  = (const float*)d_in[16];
    const float* de  = (const float*)d_in[17];
    const float* Lam = (const float*)d_in[18];

    float* out = (float*)d_out;
    float* mij = out + (size_t)NN * DD;

    cudaFuncSetAttribute(edge_kernel, cudaFuncAttributeMaxDynamicSharedMemorySize, EDGE_SMEM);
    cudaFuncSetAttribute(node_kernel, cudaFuncAttributeMaxDynamicSharedMemorySize, NODE_SMEM);

    zero_agg_kernel<<<(NN * DD / 4) / 256, 256>>>();
    edge_kernel<<<NE / 64, 256, EDGE_SMEM>>>(h, ei, ei + NE, eW1, eb1, eW2, eb2, mij);
    node_kernel<<<(NN + 63) / 64, 256, NODE_SMEM>>>(h, qW1, qb1, qW2, qb2,
                                                    pW1, pb1, pW2, pb2,
                                                    al, be, ga, de, Lam, out);
}

// round 13
// speedup vs baseline: 2.1988x; 1.3961x over previous
#include <cuda_runtime.h>
#include <cstdint>

#define NN  50000
#define NE  800000
#define DD  64
#define HID 64

// Scratch: aggregation buffer (allocation-free rule -> __device__ global)
__device__ float g_agg[NN * DD];

__device__ __forceinline__ float silu_f(float v) {
    return v * (1.0f / (1.0f + __expf(-v)));
}

// round fp32 -> tf32 (rna) ; value kept in a 32-bit float slot
__device__ __forceinline__ float tf32r(float x) {
    uint32_t u;
    asm("cvt.rna.tf32.f32 %0, %1;" : "=r"(u) : "f"(x));
    return __uint_as_float(u);
}

// m16n8k8 tf32 MMA, fp32 accumulate (legacy HMMA path on sm_103a)
__device__ __forceinline__ void mma_tf32(float* c,
    uint32_t a0, uint32_t a1, uint32_t a2, uint32_t a3,
    uint32_t b0, uint32_t b1)
{
    asm volatile(
        "mma.sync.aligned.m16n8k8.row.col.f32.tf32.tf32.f32 "
        "{%0,%1,%2,%3}, {%4,%5,%6,%7}, {%8,%9}, {%0,%1,%2,%3};"
        : "+f"(c[0]), "+f"(c[1]), "+f"(c[2]), "+f"(c[3])
        : "r"(a0), "r"(a1), "r"(a2), "r"(a3), "r"(b0), "r"(b1));
}

// ---------------- packed f32x2 helpers (node kernel) ------------------------
__device__ __forceinline__ uint64_t dupf(float x) {
    uint64_t r; asm("mov.b64 %0, {%1, %1};" : "=l"(r) : "f"(x)); return r;
}
__device__ __forceinline__ void fma2(uint64_t& d, uint64_t a, uint64_t b) {
    asm("fma.rn.f32x2 %0, %1, %2, %0;" : "+l"(d) : "l"(a), "l"(b));
}
__device__ __forceinline__ float2 unpk(uint64_t v) {
    float2 f; asm("mov.b64 {%0, %1}, %2;" : "=f"(f.x), "=f"(f.y) : "l"(v)); return f;
}
#define MICRO_K(acc, xv, wv)                                     \
    do {                                                         \
        uint64_t _dx = dupf(xv);                                 \
        fma2((acc)[0], _dx, (wv).x);                             \
        fma2((acc)[1], _dx, (wv).y);                             \
    } while (0)

// ---------------------------------------------------------------------------
// zero the aggregation scratch (must run every replay)
// ---------------------------------------------------------------------------
__global__ void zero_agg_kernel() {
    int i = blockIdx.x * blockDim.x + threadIdx.x;
    ((float4*)g_agg)[i] = make_float4(0.f, 0.f, 0.f, 0.f);
}

// ---------------------------------------------------------------------------
// Edge kernel (tensor-core tf32): 64 edges/block, 256 threads (8 warps),
// warps = 4 row-tiles(16) x 2 col-halves(32). Both layers via m16n8k8 mma.
// Smem strides: X 132 (bank 4g+tg distinct), W 72 (bank 8tg+g distinct), H 68.
// ---------------------------------------------------------------------------
#define XST 132
#define WST 72
#define HST 68
#define EDGE_SMEM ((64*XST + 128*WST + 64*WST + 64*HST) * 4 + 2 * 64 * 4)

__global__ void __launch_bounds__(256, 2) edge_kernel(
    const float* __restrict__ h, const int* __restrict__ erow, const int* __restrict__ ecol,
    const float* __restrict__ W1, const float* __restrict__ b1,
    const float* __restrict__ W2, const float* __restrict__ b2,
    float* __restrict__ mij)
{
    extern __shared__ float sm[];
    float* Xs  = sm;                     // 64 x 132
    float* W1s = Xs + 64 * XST;          // 128 x 72
    float* W2s = W1s + 128 * WST;        // 64 x 72
    float* Hs  = W2s + 64 * WST;         // 64 x 68
    int*   irs = (int*)(Hs + 64 * HST);  // 64 row ids
    int*   ics = irs + 64;               // 64 col ids

    const int tid = threadIdx.x;
    const int eb  = blockIdx.x * 64;

    if (tid < 64)       irs[tid]      = erow[eb + tid];
    else if (tid < 128) ics[tid - 64] = ecol[eb + tid - 64];
    __syncthreads();

    // gather X = [h[row] | h[col]], tf32-rounded, stride 132
    const float4* h4 = (const float4*)h;
#pragma unroll
    for (int i = 0; i < 8; i++) {
        int f = i * 256 + tid;
        int r = f >> 5, p = f & 31;
        int node = (p < 16) ? irs[r] : ics[r];
        float4 v = h4[node * 16 + (p & 15)];
        v.x = tf32r(v.x); v.y = tf32r(v.y); v.z = tf32r(v.z); v.w = tf32r(v.w);
        ((float4*)Xs)[r * 33 + p] = v;
    }
    // stage W1 [128x72] and W2 [64x72], tf32-rounded
#pragma unroll
    for (int i = 0; i < 8; i++) {
        int f = i * 256 + tid;
        int k = f >> 4, c = f & 15;
        float4 v = ((const float4*)W1)[f];
        v.x = tf32r(v.x); v.y = tf32r(v.y); v.z = tf32r(v.z); v.w = tf32r(v.w);
        ((float4*)W1s)[k * 18 + c] = v;
    }
#pragma unroll
    for (int i = 0; i < 4; i++) {
        int f = i * 256 + tid;
        int k = f >> 4, c = f & 15;
        float4 v = ((const float4*)W2)[f];
        v.x = tf32r(v.x); v.y = tf32r(v.y); v.z = tf32r(v.z); v.w = tf32r(v.w);
        ((float4*)W2s)[k * 18 + c] = v;
    }
    __syncthreads();

    const int warp = tid >> 5, lane = tid & 31;
    const int rb  = (warp >> 1) * 16;    // row-tile base
    const int nb0 = (warp & 1) * 32;     // col-half base
    const int g   = lane >> 2, tg = lane & 3;

    float acc[4][4];
#pragma unroll
    for (int t = 0; t < 4; t++)
#pragma unroll
        for (int j = 0; j < 4; j++) acc[t][j] = 0.f;

    // layer 1: [64x128] @ [128x64]
    {
        const float* A0 = Xs + (rb + g) * XST + tg;
        const float* A1 = Xs + (rb + g + 8) * XST + tg;
#pragma unroll
        for (int kk = 0; kk < 16; kk++) {
            int k0 = kk * 8;
            uint32_t a0 = __float_as_uint(A0[k0]);
            uint32_t a1 = __float_as_uint(A1[k0]);
            uint32_t a2 = __float_as_uint(A0[k0 + 4]);
            uint32_t a3 = __float_as_uint(A1[k0 + 4]);
            const float* Bp = W1s + (k0 + tg) * WST + nb0 + g;
#pragma unroll
            for (int t = 0; t < 4; t++) {
                uint32_t b0 = __float_as_uint(Bp[t * 8]);
                uint32_t bq = __float_as_uint(Bp[t * 8 + 4 * WST]);
                mma_tf32(acc[t], a0, a1, a2, a3, b0, bq);
            }
        }
    }
    // epilogue 1: bias + silu + tf32 round -> Hs
#pragma unroll
    for (int t = 0; t < 4; t++) {
        int nc = nb0 + t * 8 + 2 * tg;
        float2 bb = *(const float2*)&b1[nc];
        float2 v0, v1;
        v0.x = tf32r(silu_f(acc[t][0] + bb.x));
        v0.y = tf32r(silu_f(acc[t][1] + bb.y));
        v1.x = tf32r(silu_f(acc[t][2] + bb.x));
        v1.y = tf32r(silu_f(acc[t][3] + bb.y));
        *(float2*)&Hs[(rb + g) * HST + nc]     = v0;
        *(float2*)&Hs[(rb + g + 8) * HST + nc] = v1;
    }
    __syncthreads();

#pragma unroll
    for (int t = 0; t < 4; t++)
#pragma unroll
        for (int j = 0; j < 4; j++) acc[t][j] = 0.f;

    // layer 2: [64x64] @ [64x64]
    {
        const float* A0 = Hs + (rb + g) * HST + tg;
        const float* A1 = Hs + (rb + g + 8) * HST + tg;
#pragma unroll
        for (int kk = 0; kk < 8; kk++) {
            int k0 = kk * 8;
            uint32_t a0 = __float_as_uint(A0[k0]);
            uint32_t a1 = __float_as_uint(A1[k0]);
            uint32_t a2 = __float_as_uint(A0[k0 + 4]);
            uint32_t a3 = __float_as_uint(A1[k0 + 4]);
            const float* Bp = W2s + (k0 + tg) * WST + nb0 + g;
#pragma unroll
            for (int t = 0; t < 4; t++) {
                uint32_t b0 = __float_as_uint(Bp[t * 8]);
                uint32_t bq = __float_as_uint(Bp[t * 8 + 4 * WST]);
                mma_tf32(acc[t], a0, a1, a2, a3, b0, bq);
            }
        }
    }
    // epilogue 2: bias + silu -> mij (float2) + scatter-add into g_agg
    {
        int row0 = rb + g, row1 = rb + g + 8;
        int nd0 = irs[row0], nd1 = irs[row1];
        size_t ge0 = (size_t)(eb + row0) * 64;
        size_t ge1 = (size_t)(eb + row1) * 64;
#pragma unroll
        for (int t = 0; t < 4; t++) {
            int nc = nb0 + t * 8 + 2 * tg;
            float2 bb = *(const float2*)&b2[nc];
            float2 m0, m1;
            m0.x = silu_f(acc[t][0] + bb.x);
            m0.y = silu_f(acc[t][1] + bb.y);
            m1.x = silu_f(acc[t][2] + bb.x);
            m1.y = silu_f(acc[t][3] + bb.y);
            *(float2*)&mij[ge0 + nc] = m0;
            *(float2*)&mij[ge1 + nc] = m1;
            asm volatile("red.global.add.v2.f32 [%0], {%1,%2};"
                         :: "l"(&g_agg[(size_t)nd0 * 64 + nc]), "f"(m0.x), "f"(m0.y) : "memory");
            asm volatile("red.global.add.v2.f32 [%0], {%1,%2};"
                         :: "l"(&g_agg[(size_t)nd1 * 64 + nc]), "f"(m1.x), "f"(m1.y) : "memory");
        }
    }
}

// ---------------------------------------------------------------------------
// 3-qubit statevector circuit (per node, per thread)
// ---------------------------------------------------------------------------
__device__ __forceinline__ void apply_rx3(float* ar, float* ai, float cb, float sb) {
#pragma unroll
    for (int q = 0; q < 3; q++) {
        int st = 4 >> q;
#pragma unroll
        for (int i = 0; i < 8; i++) {
            if (i & st) continue;
            int j = i + st;
            float a0r = ar[i], a0i = ai[i], a1r = ar[j], a1i = ai[j];
            ar[i] =  cb * a0r + sb * a1i;
            ai[i] =  cb * a0i - sb * a1r;
            ar[j] =  sb * a0i + cb * a1r;
            ai[j] = -sb * a0r + cb * a1i;
        }
    }
}

__device__ __forceinline__ void apply_rz(float* ar, float* ai, int st, float theta) {
    float s, c;
    sincosf(0.5f * theta, &s, &c);
#pragma unroll
    for (int i = 0; i < 8; i++) {
        float r = ar[i], im = ai[i];
        if (i & st) { ar[i] = r * c - im * s; ai[i] = im * c + r * s; }
        else        { ar[i] = r * c + im * s; ai[i] = im * c - r * s; }
    }
}

__device__ __forceinline__ void apply_h(float* ar, float* ai, int st) {
    const float SQ = 0.70710678118654752f;
#pragma unroll
    for (int i = 0; i < 8; i++) {
        if (i & st) continue;
        int j = i + st;
        float a0r = ar[i], a0i = ai[i], a1r = ar[j], a1i = ai[j];
        ar[i] = (a0r + a1r) * SQ; ai[i] = (a0i + a1i) * SQ;
        ar[j] = (a0r - a1r) * SQ; ai[j] = (a0i - a1i) * SQ;
    }
}

__device__ void qcircuit(const float* x, float alpha, float beta, float gamma, float delta,
                         const float* __restrict__ Lam, float* outq)
{
    float ar[8], ai[8];
#pragma unroll
    for (int i = 0; i < 8; i++) { ar[i] = 0.f; ai[i] = 0.f; }
    ar[0] = 1.f;

    // 1) data-encoding RY(alpha * x_q)
#pragma unroll
    for (int q = 0; q < 3; q++) {
        float s, c;
        sincosf(0.5f * alpha * x[q], &s, &c);
        int st = 4 >> q;
#pragma unroll
        for (int i = 0; i < 8; i++) {
            if (i & st) continue;
            int j = i + st;
            float a0r = ar[i], a0i = ai[i], a1r = ar[j], a1i = ai[j];
            ar[i] = c * a0r - s * a1r; ai[i] = c * a0i - s * a1i;
            ar[j] = s * a0r + c * a1r; ai[j] = s * a0i + c * a1i;
        }
    }
    // 2) IsingZZ coupling
#pragma unroll
    for (int qi = 0; qi < 3; qi++)
#pragma unroll
        for (int qj = qi + 1; qj < 3; qj++) {
            float phi = 0.5f * gamma * (Lam[qi * 3 + qj] + Lam[qj * 3 + qi]);
            float sp, cp;
            sincosf(0.5f * phi, &sp, &cp);
#pragma unroll
            for (int i = 0; i < 8; i++) {
                int bi = (i >> (2 - qi)) & 1, bj = (i >> (2 - qj)) & 1;
                float pi = (bi ^ bj) ? sp : -sp;
                float r = ar[i] * cp - ai[i] * pi;
                ai[i]   = ar[i] * pi + ai[i] * cp;
                ar[i]   = r;
            }
        }
    // 3) kinetic RX(beta)
    float sb, cb;
    sincosf(0.5f * beta, &sb, &cb);
    apply_rx3(ar, ai, cb, sb);
    // 4) anharmonic per qubit
#pragma unroll
    for (int q = 0; q < 3; q++) {
        int st = 4 >> q;
        float x2 = x[q] * x[q];
        apply_rz(ar, ai, st, delta * (1.f - 0.5f * x2));
        apply_h(ar, ai, st);
        apply_rz(ar, ai, st, delta * x2);
        apply_h(ar, ai, st);
    }
    // 5) final RX(beta)
    apply_rx3(ar, ai, cb, sb);

    float e0 = 0.f, e1 = 0.f, e2 = 0.f;
#pragma unroll
    for (int i = 0; i < 8; i++) {
        float p = ar[i] * ar[i] + ai[i] * ai[i];
        e0 += (i & 4) ? -p : p;
        e1 += (i & 2) ? -p : p;
        e2 += (i & 1) ? -p : p;
    }
    outq[0] = e0; outq[1] = e1; outq[2] = e2;
}

// ---------------------------------------------------------------------------
// Node kernel: a=[h,agg/100]; q_in = silu(a@qW1+qb1)@qW2+qb2; q_out = circuit;
// out = h + silu([a,q_out]@pW1+pb1)@pW2+pb2.  64 nodes per block.
// ---------------------------------------------------------------------------
#define NODE_SMEM ((64*132 + 131*64 + 64*68) * 4)

__global__ void __launch_bounds__(256, 2) node_kernel(
    const float* __restrict__ h,
    const float* __restrict__ qW1, const float* __restrict__ qb1,
    const float* __restrict__ qW2, const float* __restrict__ qb2,
    const float* __restrict__ pW1, const float* __restrict__ pb1,
    const float* __restrict__ pW2, const float* __restrict__ pb2,
    const float* __restrict__ alpha_p, const float* __restrict__ beta_p,
    const float* __restrict__ gamma_p, const float* __restrict__ delta_p,
    const float* __restrict__ Lam,
    float* __restrict__ out)
{
    extern __shared__ float sm[];
    float* Xs = sm;              // 64 x 132 : [h(64) | agg/100(64) | q_out(3) | pad]
    float* Ws = Xs + 64 * 132;   // up to 131 x 64
    float* Hs = Ws + 131 * 64;   // 64 x 68

    const int tid = threadIdx.x;
    const int nb  = blockIdx.x * 64;

    const float4* h4 = (const float4*)h;
    const float4* a4 = (const float4*)g_agg;
#pragma unroll
    for (int i = 0; i < 8; i++) {
        int f = i * 256 + tid;
        int r = f >> 5, p = f & 31;
        int node = nb + r;
        float4 v = make_float4(0.f, 0.f, 0.f, 0.f);
        if (node < NN) {
            if (p < 16) v = h4[node * 16 + p];
            else {
                v = a4[node * 16 + (p - 16)];
                v.x *= 0.01f; v.y *= 0.01f; v.z *= 0.01f; v.w *= 0.01f;
            }
        }
        ((float4*)Xs)[r * 33 + p] = v;
    }
    if (tid < 64) ((float4*)Xs)[tid * 33 + 32] = make_float4(0.f, 0.f, 0.f, 0.f);

    float4* Ws4 = (float4*)Ws;
#pragma unroll
    for (int i = 0; i < 8; i++) Ws4[i * 256 + tid] = ((const float4*)qW1)[i * 256 + tid];
    __syncthreads();

    const int tx = tid & 15, ty = tid >> 4;
    const int r0 = ty * 4, c0 = tx * 4;
    uint64_t acc[4][2];

    // phase A: H = silu(X[:, :128] @ qW1 + qb1), k-blocked by 4
#pragma unroll
    for (int i = 0; i < 4; i++) { acc[i][0] = 0ull; acc[i][1] = 0ull; }
#pragma unroll 2
    for (int k4 = 0; k4 < 128; k4 += 4) {
        ulonglong2 w0 = *(const ulonglong2*)&Ws[(k4 + 0) * 64 + c0];
        ulonglong2 w1 = *(const ulonglong2*)&Ws[(k4 + 1) * 64 + c0];
        ulonglong2 w2 = *(const ulonglong2*)&Ws[(k4 + 2) * 64 + c0];
        ulonglong2 w3 = *(const ulonglong2*)&Ws[(k4 + 3) * 64 + c0];
#pragma unroll
        for (int i = 0; i < 4; i++) {
            float4 xv = *(const float4*)&Xs[(r0 + i) * 132 + k4];
            MICRO_K(acc[i], xv.x, w0);
            MICRO_K(acc[i], xv.y, w1);
            MICRO_K(acc[i], xv.z, w2);
            MICRO_K(acc[i], xv.w, w3);
        }
    }
    {
        float4 bb = *(const float4*)&qb1[c0];
#pragma unroll
        for (int i = 0; i < 4; i++) {
            float2 p0 = unpk(acc[i][0]), p1 = unpk(acc[i][1]);
            float4 v;
            v.x = silu_f(p0.x + bb.x);
            v.y = silu_f(p0.y + bb.y);
            v.z = silu_f(p1.x + bb.z);
            v.w = silu_f(p1.y + bb.w);
            *(float4*)&Hs[(r0 + i) * 68 + c0] = v;
        }
    }
    __syncthreads();

    // phase B: q_in = H @ qW2 + qb2 ; quantum circuit (one thread per node)
    if (tid < 64) {
        float qin[3] = { qb2[0], qb2[1], qb2[2] };
        for (int k = 0; k < 64; k++) {
            float hv = Hs[tid * 68 + k];
            qin[0] += hv * qW2[k * 3 + 0];
            qin[1] += hv * qW2[k * 3 + 1];
            qin[2] += hv * qW2[k * 3 + 2];
        }
        float qo[3];
        qcircuit(qin, *alpha_p, *beta_p, *gamma_p, *delta_p, Lam, qo);
        Xs[tid * 132 + 128] = qo[0];
        Xs[tid * 132 + 129] = qo[1];
        Xs[tid * 132 + 130] = qo[2];
    }
    __syncthreads();

    // stage pW1 (131x64)
    for (int f = tid; f < 2096; f += 256) Ws4[f] = ((const float4*)pW1)[f];
    __syncthreads();

    // phase C: P = silu(X[:, :131] @ pW1 + pb1), k-blocked by 4 + 3-tail
#pragma unroll
    for (int i = 0; i < 4; i++) { acc[i][0] = 0ull; acc[i][1] = 0ull; }
#pragma unroll 2
    for (int k4 = 0; k4 < 128; k4 += 4) {
        ulonglong2 w0 = *(const ulonglong2*)&Ws[(k4 + 0) * 64 + c0];
        ulonglong2 w1 = *(const ulonglong2*)&Ws[(k4 + 1) * 64 + c0];
        ulonglong2 w2 = *(const ulonglong2*)&Ws[(k4 + 2) * 64 + c0];
        ulonglong2 w3 = *(const ulonglong2*)&Ws[(k4 + 3) * 64 + c0];
#pragma unroll
        for (int i = 0; i < 4; i++) {
            float4 xv = *(const float4*)&Xs[(r0 + i) * 132 + k4];
            MICRO_K(acc[i], xv.x, w0);
            MICRO_K(acc[i], xv.y, w1);
            MICRO_K(acc[i], xv.z, w2);
            MICRO_K(acc[i], xv.w, w3);
        }
    }
#pragma unroll
    for (int k = 128; k < 131; k++) {
        ulonglong2 wv = *(const ulonglong2*)&Ws[k * 64 + c0];
#pragma unroll
        for (int i = 0; i < 4; i++) {
            MICRO_K(acc[i], Xs[(r0 + i) * 132 + k], wv);
        }
    }
    {
        float4 bb = *(const float4*)&pb1[c0];
#pragma unroll
        for (int i = 0; i < 4; i++) {
            float2 p0 = unpk(acc[i][0]), p1 = unpk(acc[i][1]);
            float4 v;
            v.x = silu_f(p0.x + bb.x);
            v.y = silu_f(p0.y + bb.y);
            v.z = silu_f(p1.x + bb.z);
            v.w = silu_f(p1.y + bb.w);
            *(float4*)&Hs[(r0 + i) * 68 + c0] = v;
        }
    }
    __syncthreads();

    // stage pW2 (64x64)
    for (int f = tid; f < 1024; f += 256) Ws4[f] = ((const float4*)pW2)[f];
    __syncthreads();

    // phase D: out = h + P @ pW2 + pb2, k-blocked by 4
#pragma unroll
    for (int i = 0; i < 4; i++) { acc[i][0] = 0ull; acc[i][1] = 0ull; }
#pragma unroll 2
    for (int k4 = 0; k4 < 64; k4 += 4) {
        ulonglong2 w0 = *(const ulonglong2*)&Ws[(k4 + 0) * 64 + c0];
        ulonglong2 w1 = *(const ulonglong2*)&Ws[(k4 + 1) * 64 + c0];
        ulonglong2 w2 = *(const ulonglong2*)&Ws[(k4 + 2) * 64 + c0];
        ulonglong2 w3 = *(const ulonglong2*)&Ws[(k4 + 3) * 64 + c0];
#pragma unroll
        for (int i = 0; i < 4; i++) {
            float4 xv = *(const float4*)&Hs[(r0 + i) * 68 + k4];
            MICRO_K(acc[i], xv.x, w0);
            MICRO_K(acc[i], xv.y, w1);
            MICRO_K(acc[i], xv.z, w2);
            MICRO_K(acc[i], xv.w, w3);
        }
    }
    float4 bb = *(const float4*)&pb2[c0];
#pragma unroll
    for (int i = 0; i < 4; i++) {
        int node = nb + r0 + i;
        if (node < NN) {
            float2 p0 = unpk(acc[i][0]), p1 = unpk(acc[i][1]);
            float4 v;
            v.x = Xs[(r0 + i) * 132 + c0 + 0] + p0.x + bb.x;
            v.y = Xs[(r0 + i) * 132 + c0 + 1] + p0.y + bb.y;
            v.z = Xs[(r0 + i) * 132 + c0 + 2] + p1.x + bb.z;
            v.w = Xs[(r0 + i) * 132 + c0 + 3] + p1.y + bb.w;
            *(float4*)&out[(size_t)node * 64 + c0] = v;
        }
    }
}

// ---------------------------------------------------------------------------
extern "C" void kernel_launch(void* const* d_in, const int* in_sizes, int n_in,
                              void* d_out, int out_size) {
    const float* h   = (const float*)d_in[0];
    const int*   ei  = (const int*)d_in[1];
    const float* eW1 = (const float*)d_in[2];
    const float* eb1 = (const float*)d_in[3];
    const float* eW2 = (const float*)d_in[4];
    const float* eb2 = (const float*)d_in[5];
    const float* qW1 = (const float*)d_in[6];
    const float* qb1 = (const float*)d_in[7];
    const float* qW2 = (const float*)d_in[8];
    const float* qb2 = (const float*)d_in[9];
    const float* pW1 = (const float*)d_in[10];
    const float* pb1 = (const float*)d_in[11];
    const float* pW2 = (const float*)d_in[12];
    const float* pb2 = (const float*)d_in[13];
    const float* al  = (const float*)d_in[14];
    const float* be  = (const float*)d_in[15];
    const float* ga  = (const float*)d_in[16];
    const float* de  = (const float*)d_in[17];
    const float* Lam = (const float*)d_in[18];

    float* out = (float*)d_out;
    float* mij = out + (size_t)NN * DD;

    cudaFuncSetAttribute(edge_kernel, cudaFuncAttributeMaxDynamicSharedMemorySize, EDGE_SMEM);
    cudaFuncSetAttribute(node_kernel, cudaFuncAttributeMaxDynamicSharedMemorySize, NODE_SMEM);

    zero_agg_kernel<<<(NN * DD / 4) / 256, 256>>>();
    edge_kernel<<<NE / 64, 256, EDGE_SMEM>>>(h, ei, ei + NE, eW1, eb1, eW2, eb2, mij);
    node_kernel<<<(NN + 63) / 64, 256, NODE_SMEM>>>(h, qW1, qb1, qW2, qb2,
                                                    pW1, pb1, pW2, pb2,
                                                    al, be, ga, de, Lam, out);
}

// round 14
// speedup vs baseline: 2.3191x; 1.0547x over previous
#include <cuda_runtime.h>
#include <cstdint>

#define NN  50000
#define NE  800000
#define DD  64
#define HID 64

// Scratch: aggregation buffer (allocation-free rule -> __device__ global)
__device__ float g_agg[NN * DD];

__device__ __forceinline__ float silu_f(float v) {
    return v * (1.0f / (1.0f + __expf(-v)));
}

// round fp32 -> tf32 (rna); value kept in a 32-bit float slot
__device__ __forceinline__ float tf32r(float x) {
    uint32_t u;
    asm("cvt.rna.tf32.f32 %0, %1;" : "=r"(u) : "f"(x));
    return __uint_as_float(u);
}
// round fp32 -> tf32 bits
__device__ __forceinline__ uint32_t tf32u(float x) {
    uint32_t u;
    asm("cvt.rna.tf32.f32 %0, %1;" : "=r"(u) : "f"(x));
    return u;
}

// m16n8k8 tf32 MMA, fp32 accumulate
__device__ __forceinline__ void mma_tf32(float* c,
    uint32_t a0, uint32_t a1, uint32_t a2, uint32_t a3,
    uint32_t b0, uint32_t b1)
{
    asm volatile(
        "mma.sync.aligned.m16n8k8.row.col.f32.tf32.tf32.f32 "
        "{%0,%1,%2,%3}, {%4,%5,%6,%7}, {%8,%9}, {%0,%1,%2,%3};"
        : "+f"(c[0]), "+f"(c[1]), "+f"(c[2]), "+f"(c[3])
        : "r"(a0), "r"(a1), "r"(a2), "r"(a3), "r"(b0), "r"(b1));
}

// ---------------------------------------------------------------------------
// zero the aggregation scratch (must run every replay)
// ---------------------------------------------------------------------------
__global__ void zero_agg_kernel() {
    int i = blockIdx.x * blockDim.x + threadIdx.x;
    ((float4*)g_agg)[i] = make_float4(0.f, 0.f, 0.f, 0.f);
}

// ---------------------------------------------------------------------------
// Edge kernel (tensor-core tf32): 64 edges/block, 256 threads (8 warps),
// warps = 4 row-tiles(16) x 2 col-halves(32). Both layers via m16n8k8 mma.
// ---------------------------------------------------------------------------
#define XST 132
#define WST 72
#define HST 68
#define EDGE_SMEM ((64*XST + 128*WST + 64*WST + 64*HST) * 4 + 2 * 64 * 4)

__global__ void __launch_bounds__(256, 2) edge_kernel(
    const float* __restrict__ h, const int* __restrict__ erow, const int* __restrict__ ecol,
    const float* __restrict__ W1, const float* __restrict__ b1,
    const float* __restrict__ W2, const float* __restrict__ b2,
    float* __restrict__ mij)
{
    extern __shared__ float sm[];
    float* Xs  = sm;                     // 64 x 132
    float* W1s = Xs + 64 * XST;          // 128 x 72
    float* W2s = W1s + 128 * WST;        // 64 x 72
    float* Hs  = W2s + 64 * WST;         // 64 x 68
    int*   irs = (int*)(Hs + 64 * HST);  // 64 row ids
    int*   ics = irs + 64;               // 64 col ids

    const int tid = threadIdx.x;
    const int eb  = blockIdx.x * 64;

    if (tid < 64)       irs[tid]      = erow[eb + tid];
    else if (tid < 128) ics[tid - 64] = ecol[eb + tid - 64];
    __syncthreads();

    // gather X = [h[row] | h[col]], tf32-rounded, stride 132
    const float4* h4 = (const float4*)h;
#pragma unroll
    for (int i = 0; i < 8; i++) {
        int f = i * 256 + tid;
        int r = f >> 5, p = f & 31;
        int node = (p < 16) ? irs[r] : ics[r];
        float4 v = h4[node * 16 + (p & 15)];
        v.x = tf32r(v.x); v.y = tf32r(v.y); v.z = tf32r(v.z); v.w = tf32r(v.w);
        ((float4*)Xs)[r * 33 + p] = v;
    }
    // stage W1 [128x72] and W2 [64x72], tf32-rounded
#pragma unroll
    for (int i = 0; i < 8; i++) {
        int f = i * 256 + tid;
        int k = f >> 4, c = f & 15;
        float4 v = ((const float4*)W1)[f];
        v.x = tf32r(v.x); v.y = tf32r(v.y); v.z = tf32r(v.z); v.w = tf32r(v.w);
        ((float4*)W1s)[k * 18 + c] = v;
    }
#pragma unroll
    for (int i = 0; i < 4; i++) {
        int f = i * 256 + tid;
        int k = f >> 4, c = f & 15;
        float4 v = ((const float4*)W2)[f];
        v.x = tf32r(v.x); v.y = tf32r(v.y); v.z = tf32r(v.z); v.w = tf32r(v.w);
        ((float4*)W2s)[k * 18 + c] = v;
    }
    __syncthreads();

    const int warp = tid >> 5, lane = tid & 31;
    const int rb  = (warp >> 1) * 16;    // row-tile base
    const int nb0 = (warp & 1) * 32;     // col-half base
    const int g   = lane >> 2, tg = lane & 3;

    float acc[4][4];
#pragma unroll
    for (int t = 0; t < 4; t++)
#pragma unroll
        for (int j = 0; j < 4; j++) acc[t][j] = 0.f;

    // layer 1: [64x128] @ [128x64]
    {
        const float* A0 = Xs + (rb + g) * XST + tg;
        const float* A1 = Xs + (rb + g + 8) * XST + tg;
#pragma unroll
        for (int kk = 0; kk < 16; kk++) {
            int k0 = kk * 8;
            uint32_t a0 = __float_as_uint(A0[k0]);
            uint32_t a1 = __float_as_uint(A1[k0]);
            uint32_t a2 = __float_as_uint(A0[k0 + 4]);
            uint32_t a3 = __float_as_uint(A1[k0 + 4]);
            const float* Bp = W1s + (k0 + tg) * WST + nb0 + g;
#pragma unroll
            for (int t = 0; t < 4; t++) {
                uint32_t b0 = __float_as_uint(Bp[t * 8]);
                uint32_t bq = __float_as_uint(Bp[t * 8 + 4 * WST]);
                mma_tf32(acc[t], a0, a1, a2, a3, b0, bq);
            }
        }
    }
    // epilogue 1: bias + silu + tf32 round -> Hs
#pragma unroll
    for (int t = 0; t < 4; t++) {
        int nc = nb0 + t * 8 + 2 * tg;
        float2 bb = *(const float2*)&b1[nc];
        float2 v0, v1;
        v0.x = tf32r(silu_f(acc[t][0] + bb.x));
        v0.y = tf32r(silu_f(acc[t][1] + bb.y));
        v1.x = tf32r(silu_f(acc[t][2] + bb.x));
        v1.y = tf32r(silu_f(acc[t][3] + bb.y));
        *(float2*)&Hs[(rb + g) * HST + nc]     = v0;
        *(float2*)&Hs[(rb + g + 8) * HST + nc] = v1;
    }
    __syncthreads();

#pragma unroll
    for (int t = 0; t < 4; t++)
#pragma unroll
        for (int j = 0; j < 4; j++) acc[t][j] = 0.f;

    // layer 2: [64x64] @ [64x64]
    {
        const float* A0 = Hs + (rb + g) * HST + tg;
        const float* A1 = Hs + (rb + g + 8) * HST + tg;
#pragma unroll
        for (int kk = 0; kk < 8; kk++) {
            int k0 = kk * 8;
            uint32_t a0 = __float_as_uint(A0[k0]);
            uint32_t a1 = __float_as_uint(A1[k0]);
            uint32_t a2 = __float_as_uint(A0[k0 + 4]);
            uint32_t a3 = __float_as_uint(A1[k0 + 4]);
            const float* Bp = W2s + (k0 + tg) * WST + nb0 + g;
#pragma unroll
            for (int t = 0; t < 4; t++) {
                uint32_t b0 = __float_as_uint(Bp[t * 8]);
                uint32_t bq = __float_as_uint(Bp[t * 8 + 4 * WST]);
                mma_tf32(acc[t], a0, a1, a2, a3, b0, bq);
            }
        }
    }
    // epilogue 2: bias + silu -> mij (float2) + scatter-add into g_agg
    {
        int row0 = rb + g, row1 = rb + g + 8;
        int nd0 = irs[row0], nd1 = irs[row1];
        size_t ge0 = (size_t)(eb + row0) * 64;
        size_t ge1 = (size_t)(eb + row1) * 64;
#pragma unroll
        for (int t = 0; t < 4; t++) {
            int nc = nb0 + t * 8 + 2 * tg;
            float2 bb = *(const float2*)&b2[nc];
            float2 m0, m1;
            m0.x = silu_f(acc[t][0] + bb.x);
            m0.y = silu_f(acc[t][1] + bb.y);
            m1.x = silu_f(acc[t][2] + bb.x);
            m1.y = silu_f(acc[t][3] + bb.y);
            *(float2*)&mij[ge0 + nc] = m0;
            *(float2*)&mij[ge1 + nc] = m1;
            asm volatile("red.global.add.v2.f32 [%0], {%1,%2};"
                         :: "l"(&g_agg[(size_t)nd0 * 64 + nc]), "f"(m0.x), "f"(m0.y) : "memory");
            asm volatile("red.global.add.v2.f32 [%0], {%1,%2};"
                         :: "l"(&g_agg[(size_t)nd1 * 64 + nc]), "f"(m1.x), "f"(m1.y) : "memory");
        }
    }
}

// ---------------------------------------------------------------------------
// 3-qubit statevector circuit (per node, per thread)
// ---------------------------------------------------------------------------
__device__ __forceinline__ void apply_rx3(float* ar, float* ai, float cb, float sb) {
#pragma unroll
    for (int q = 0; q < 3; q++) {
        int st = 4 >> q;
#pragma unroll
        for (int i = 0; i < 8; i++) {
            if (i & st) continue;
            int j = i + st;
            float a0r = ar[i], a0i = ai[i], a1r = ar[j], a1i = ai[j];
            ar[i] =  cb * a0r + sb * a1i;
            ai[i] =  cb * a0i - sb * a1r;
            ar[j] =  sb * a0i + cb * a1r;
            ai[j] = -sb * a0r + cb * a1i;
        }
    }
}

__device__ __forceinline__ void apply_rz(float* ar, float* ai, int st, float theta) {
    float s, c;
    sincosf(0.5f * theta, &s, &c);
#pragma unroll
    for (int i = 0; i < 8; i++) {
        float r = ar[i], im = ai[i];
        if (i & st) { ar[i] = r * c - im * s; ai[i] = im * c + r * s; }
        else        { ar[i] = r * c + im * s; ai[i] = im * c - r * s; }
    }
}

__device__ __forceinline__ void apply_h(float* ar, float* ai, int st) {
    const float SQ = 0.70710678118654752f;
#pragma unroll
    for (int i = 0; i < 8; i++) {
        if (i & st) continue;
        int j = i + st;
        float a0r = ar[i], a0i = ai[i], a1r = ar[j], a1i = ai[j];
        ar[i] = (a0r + a1r) * SQ; ai[i] = (a0i + a1i) * SQ;
        ar[j] = (a0r - a1r) * SQ; ai[j] = (a0i - a1i) * SQ;
    }
}

__device__ void qcircuit(const float* x, float alpha, float beta, float gamma, float delta,
                         const float* __restrict__ Lam, float* outq)
{
    float ar[8], ai[8];
#pragma unroll
    for (int i = 0; i < 8; i++) { ar[i] = 0.f; ai[i] = 0.f; }
    ar[0] = 1.f;

#pragma unroll
    for (int q = 0; q < 3; q++) {
        float s, c;
        sincosf(0.5f * alpha * x[q], &s, &c);
        int st = 4 >> q;
#pragma unroll
        for (int i = 0; i < 8; i++) {
            if (i & st) continue;
            int j = i + st;
            float a0r = ar[i], a0i = ai[i], a1r = ar[j], a1i = ai[j];
            ar[i] = c * a0r - s * a1r; ai[i] = c * a0i - s * a1i;
            ar[j] = s * a0r + c * a1r; ai[j] = s * a0i + c * a1i;
        }
    }
#pragma unroll
    for (int qi = 0; qi < 3; qi++)
#pragma unroll
        for (int qj = qi + 1; qj < 3; qj++) {
            float phi = 0.5f * gamma * (Lam[qi * 3 + qj] + Lam[qj * 3 + qi]);
            float sp, cp;
            sincosf(0.5f * phi, &sp, &cp);
#pragma unroll
            for (int i = 0; i < 8; i++) {
                int bi = (i >> (2 - qi)) & 1, bj = (i >> (2 - qj)) & 1;
                float pi = (bi ^ bj) ? sp : -sp;
                float r = ar[i] * cp - ai[i] * pi;
                ai[i]   = ar[i] * pi + ai[i] * cp;
                ar[i]   = r;
            }
        }
    float sb, cb;
    sincosf(0.5f * beta, &sb, &cb);
    apply_rx3(ar, ai, cb, sb);
#pragma unroll
    for (int q = 0; q < 3; q++) {
        int st = 4 >> q;
        float x2 = x[q] * x[q];
        apply_rz(ar, ai, st, delta * (1.f - 0.5f * x2));
        apply_h(ar, ai, st);
        apply_rz(ar, ai, st, delta * x2);
        apply_h(ar, ai, st);
    }
    apply_rx3(ar, ai, cb, sb);

    float e0 = 0.f, e1 = 0.f, e2 = 0.f;
#pragma unroll
    for (int i = 0; i < 8; i++) {
        float p = ar[i] * ar[i] + ai[i] * ai[i];
        e0 += (i & 4) ? -p : p;
        e1 += (i & 2) ? -p : p;
        e2 += (i & 1) ? -p : p;
    }
    outq[0] = e0; outq[1] = e1; outq[2] = e2;
}

// ---------------------------------------------------------------------------
// Node kernel (tensor-core tf32): 64 nodes/block, 256 threads (8 warps).
// Xs kept fp32 (exact residual + circuit I/O); A-operands cvt-on-load.
// Weights pre-rounded tf32 in smem stride 72; Ws reused for qW1/pW1/pW2.
// ---------------------------------------------------------------------------
#define NXST 132
#define NWST 72
#define NHST 68
#define NODE_SMEM ((64*NXST + 131*NWST + 64*NHST) * 4)

__global__ void __launch_bounds__(256, 2) node_kernel(
    const float* __restrict__ h,
    const float* __restrict__ qW1, const float* __restrict__ qb1,
    const float* __restrict__ qW2, const float* __restrict__ qb2,
    const float* __restrict__ pW1, const float* __restrict__ pb1,
    const float* __restrict__ pW2, const float* __restrict__ pb2,
    const float* __restrict__ alpha_p, const float* __restrict__ beta_p,
    const float* __restrict__ gamma_p, const float* __restrict__ delta_p,
    const float* __restrict__ Lam,
    float* __restrict__ out)
{
    extern __shared__ float sm[];
    float* Xs = sm;                 // 64 x 132 fp32: [h(64) | agg/100(64) | q_out(3) | pad]
    float* Ws = Xs + 64 * NXST;     // up to 131 x 72 (tf32-rounded weights)
    float* Hs = Ws + 131 * NWST;    // 64 x 68

    const int tid = threadIdx.x;
    const int nb  = blockIdx.x * 64;

    // gather X (fp32, unrounded)
    const float4* h4 = (const float4*)h;
    const float4* a4 = (const float4*)g_agg;
#pragma unroll
    for (int i = 0; i < 8; i++) {
        int f = i * 256 + tid;
        int r = f >> 5, p = f & 31;
        int node = nb + r;
        float4 v = make_float4(0.f, 0.f, 0.f, 0.f);
        if (node < NN) {
            if (p < 16) v = h4[node * 16 + p];
            else {
                v = a4[node * 16 + (p - 16)];
                v.x *= 0.01f; v.y *= 0.01f; v.z *= 0.01f; v.w *= 0.01f;
            }
        }
        ((float4*)Xs)[r * 33 + p] = v;
    }
    if (tid < 64) ((float4*)Xs)[tid * 33 + 32] = make_float4(0.f, 0.f, 0.f, 0.f);

    // stage qW1 [128x72], tf32-rounded
#pragma unroll
    for (int i = 0; i < 8; i++) {
        int f = i * 256 + tid;
        int k = f >> 4, c = f & 15;
        float4 v = ((const float4*)qW1)[f];
        v.x = tf32r(v.x); v.y = tf32r(v.y); v.z = tf32r(v.z); v.w = tf32r(v.w);
        ((float4*)Ws)[k * 18 + c] = v;
    }
    __syncthreads();

    const int warp = tid >> 5, lane = tid & 31;
    const int rb  = (warp >> 1) * 16;
    const int nb0 = (warp & 1) * 32;
    const int g   = lane >> 2, tg = lane & 3;

    float acc[4][4];
#pragma unroll
    for (int t = 0; t < 4; t++)
#pragma unroll
        for (int j = 0; j < 4; j++) acc[t][j] = 0.f;

    // phase A: H = silu(X[:, :128] @ qW1 + qb1)
    {
        const float* A0 = Xs + (rb + g) * NXST + tg;
        const float* A1 = Xs + (rb + g + 8) * NXST + tg;
#pragma unroll
        for (int kk = 0; kk < 16; kk++) {
            int k0 = kk * 8;
            uint32_t a0 = tf32u(A0[k0]);
            uint32_t a1 = tf32u(A1[k0]);
            uint32_t a2 = tf32u(A0[k0 + 4]);
            uint32_t a3 = tf32u(A1[k0 + 4]);
            const float* Bp = Ws + (k0 + tg) * NWST + nb0 + g;
#pragma unroll
            for (int t = 0; t < 4; t++) {
                uint32_t b0 = __float_as_uint(Bp[t * 8]);
                uint32_t bq = __float_as_uint(Bp[t * 8 + 4 * NWST]);
                mma_tf32(acc[t], a0, a1, a2, a3, b0, bq);
            }
        }
    }
#pragma unroll
    for (int t = 0; t < 4; t++) {
        int nc = nb0 + t * 8 + 2 * tg;
        float2 bb = *(const float2*)&qb1[nc];
        float2 v0, v1;
        v0.x = silu_f(acc[t][0] + bb.x);
        v0.y = silu_f(acc[t][1] + bb.y);
        v1.x = silu_f(acc[t][2] + bb.x);
        v1.y = silu_f(acc[t][3] + bb.y);
        *(float2*)&Hs[(rb + g) * NHST + nc]     = v0;
        *(float2*)&Hs[(rb + g + 8) * NHST + nc] = v1;
    }
    __syncthreads();

    // phase B: q_in = H @ qW2 + qb2 ; quantum circuit (one thread per node)
    if (tid < 64) {
        float qin[3] = { qb2[0], qb2[1], qb2[2] };
        for (int k = 0; k < 64; k++) {
            float hv = Hs[tid * NHST + k];
            qin[0] += hv * qW2[k * 3 + 0];
            qin[1] += hv * qW2[k * 3 + 1];
            qin[2] += hv * qW2[k * 3 + 2];
        }
        float qo[3];
        qcircuit(qin, *alpha_p, *beta_p, *gamma_p, *delta_p, Lam, qo);
        Xs[tid * NXST + 128] = qo[0];
        Xs[tid * NXST + 129] = qo[1];
        Xs[tid * NXST + 130] = qo[2];
    }
    __syncthreads();

    // stage pW1 [131x72], tf32-rounded
    for (int f = tid; f < 131 * 16; f += 256) {
        int k = f >> 4, c = f & 15;
        float4 v = ((const float4*)pW1)[f];
        v.x = tf32r(v.x); v.y = tf32r(v.y); v.z = tf32r(v.z); v.w = tf32r(v.w);
        ((float4*)Ws)[k * 18 + c] = v;
    }
    __syncthreads();

    // phase C: P = silu(X[:, :131] @ pW1 + pb1)  (MMA k=0..127 + fp32 tail)
#pragma unroll
    for (int t = 0; t < 4; t++)
#pragma unroll
        for (int j = 0; j < 4; j++) acc[t][j] = 0.f;
    {
        const float* A0 = Xs + (rb + g) * NXST + tg;
        const float* A1 = Xs + (rb + g + 8) * NXST + tg;
#pragma unroll
        for (int kk = 0; kk < 16; kk++) {
            int k0 = kk * 8;
            uint32_t a0 = tf32u(A0[k0]);
            uint32_t a1 = tf32u(A1[k0]);
            uint32_t a2 = tf32u(A0[k0 + 4]);
            uint32_t a3 = tf32u(A1[k0 + 4]);
            const float* Bp = Ws + (k0 + tg) * NWST + nb0 + g;
#pragma unroll
            for (int t = 0; t < 4; t++) {
                uint32_t b0 = __float_as_uint(Bp[t * 8]);
                uint32_t bq = __float_as_uint(Bp[t * 8 + 4 * NWST]);
                mma_tf32(acc[t], a0, a1, a2, a3, b0, bq);
            }
        }
        // fp32 tail k = 128..130 (q_out columns)
#pragma unroll
        for (int k = 128; k < 131; k++) {
            float xa = Xs[(rb + g) * NXST + k];
            float xb = Xs[(rb + g + 8) * NXST + k];
#pragma unroll
            for (int t = 0; t < 4; t++) {
                int nc = nb0 + t * 8 + 2 * tg;
                float w0 = Ws[k * NWST + nc];
                float w1 = Ws[k * NWST + nc + 1];
                acc[t][0] += xa * w0; acc[t][1] += xa * w1;
                acc[t][2] += xb * w0; acc[t][3] += xb * w1;
            }
        }
    }
#pragma unroll
    for (int t = 0; t < 4; t++) {
        int nc = nb0 + t * 8 + 2 * tg;
        float2 bb = *(const float2*)&pb1[nc];
        float2 v0, v1;
        v0.x = tf32r(silu_f(acc[t][0] + bb.x));
        v0.y = tf32r(silu_f(acc[t][1] + bb.y));
        v1.x = tf32r(silu_f(acc[t][2] + bb.x));
        v1.y = tf32r(silu_f(acc[t][3] + bb.y));
        *(float2*)&Hs[(rb + g) * NHST + nc]     = v0;
        *(float2*)&Hs[(rb + g + 8) * NHST + nc] = v1;
    }
    __syncthreads();

    // stage pW2 [64x72], tf32-rounded
    for (int f = tid; f < 64 * 16; f += 256) {
        int k = f >> 4, c = f & 15;
        float4 v = ((const float4*)pW2)[f];
        v.x = tf32r(v.x); v.y = tf32r(v.y); v.z = tf32r(v.z); v.w = tf32r(v.w);
        ((float4*)Ws)[k * 18 + c] = v;
    }
    __syncthreads();

    // phase D: out = h + P @ pW2 + pb2
#pragma unroll
    for (int t = 0; t < 4; t++)
#pragma unroll
        for (int j = 0; j < 4; j++) acc[t][j] = 0.f;
    {
        const float* A0 = Hs + (rb + g) * NHST + tg;
        const float* A1 = Hs + (rb + g + 8) * NHST + tg;
#pragma unroll
        for (int kk = 0; kk < 8; kk++) {
            int k0 = kk * 8;
            uint32_t a0 = __float_as_uint(A0[k0]);
            uint32_t a1 = __float_as_uint(A1[k0]);
            uint32_t a2 = __float_as_uint(A0[k0 + 4]);
            uint32_t a3 = __float_as_uint(A1[k0 + 4]);
            const float* Bp = Ws + (k0 + tg) * NWST + nb0 + g;
#pragma unroll
            for (int t = 0; t < 4; t++) {
                uint32_t b0 = __float_as_uint(Bp[t * 8]);
                uint32_t bq = __float_as_uint(Bp[t * 8 + 4 * NWST]);
                mma_tf32(acc[t], a0, a1, a2, a3, b0, bq);
            }
        }
    }
    {
        int row0 = rb + g, row1 = rb + g + 8;
        int n0 = nb + row0, n1 = nb + row1;
#pragma unroll
        for (int t = 0; t < 4; t++) {
            int nc = nb0 + t * 8 + 2 * tg;
            float2 bb = *(const float2*)&pb2[nc];
            if (n0 < NN) {
                float2 v;
                v.x = Xs[row0 * NXST + nc]     + acc[t][0] + bb.x;
                v.y = Xs[row0 * NXST + nc + 1] + acc[t][1] + bb.y;
                *(float2*)&out[(size_t)n0 * 64 + nc] = v;
            }
            if (n1 < NN) {
                float2 v;
                v.x = Xs[row1 * NXST + nc]     + acc[t][2] + bb.x;
                v.y = Xs[row1 * NXST + nc + 1] + acc[t][3] + bb.y;
                *(float2*)&out[(size_t)n1 * 64 + nc] = v;
            }
        }
    }
}

// ---------------------------------------------------------------------------
extern "C" void kernel_launch(void* const* d_in, const int* in_sizes, int n_in,
                              void* d_out, int out_size) {
    const float* h   = (const float*)d_in[0];
    const int*   ei  = (const int*)d_in[1];
    const float* eW1 = (const float*)d_in[2];
    const float* eb1 = (const float*)d_in[3];
    const float* eW2 = (const float*)d_in[4];
    const float* eb2 = (const float*)d_in[5];
    const float* qW1 = (const float*)d_in[6];
    const float* qb1 = (const float*)d_in[7];
    const float* qW2 = (const float*)d_in[8];
    const float* qb2 = (const float*)d_in[9];
    const float* pW1 = (const float*)d_in[10];
    const float* pb1 = (const float*)d_in[11];
    const float* pW2 = (const float*)d_in[12];
    const float* pb2 = (const float*)d_in[13];
    const float* al  = (const float*)d_in[14];
    const float* be  = (const float*)d_in[15];
    const float* ga  = (const float*)d_in[16];
    const float* de  = (const float*)d_in[17];
    const float* Lam = (const float*)d_in[18];

    float* out = (float*)d_out;
    float* mij = out + (size_t)NN * DD;

    cudaFuncSetAttribute(edge_kernel, cudaFuncAttributeMaxDynamicSharedMemorySize, EDGE_SMEM);
    cudaFuncSetAttribute(node_kernel, cudaFuncAttributeMaxDynamicSharedMemorySize, NODE_SMEM);

    zero_agg_kernel<<<(NN * DD / 4) / 256, 256>>>();
    edge_kernel<<<NE / 64, 256, EDGE_SMEM>>>(h, ei, ei + NE, eW1, eb1, eW2, eb2, mij);
    node_kernel<<<(NN + 63) / 64, 256, NODE_SMEM>>>(h, qW1, qb1, qW2, qb2,
                                                    pW1, pb1, pW2, pb2,
                                                    al, be, ga, de, Lam, out);
}

// round 15
// speedup vs baseline: 2.8590x; 1.2328x over previous
#include <cuda_runtime.h>
#include <cstdint>

#define NN  50000
#define NE  800000
#define DD  64
#define HID 64
#define NTILES (NE / 64)
#define EDGE_GRID 296

// Scratch: aggregation buffer (allocation-free rule -> __device__ global)
__device__ float g_agg[NN * DD];

__device__ __forceinline__ float silu_f(float v) {
    return v * (1.0f / (1.0f + __expf(-v)));
}

// round fp32 -> tf32 (rna); value kept in a 32-bit float slot
__device__ __forceinline__ float tf32r(float x) {
    uint32_t u;
    asm("cvt.rna.tf32.f32 %0, %1;" : "=r"(u) : "f"(x));
    return __uint_as_float(u);
}
// round fp32 -> tf32 bits
__device__ __forceinline__ uint32_t tf32u(float x) {
    uint32_t u;
    asm("cvt.rna.tf32.f32 %0, %1;" : "=r"(u) : "f"(x));
    return u;
}

// m16n8k8 tf32 MMA, fp32 accumulate
__device__ __forceinline__ void mma_tf32(float* c,
    uint32_t a0, uint32_t a1, uint32_t a2, uint32_t a3,
    uint32_t b0, uint32_t b1)
{
    asm volatile(
        "mma.sync.aligned.m16n8k8.row.col.f32.tf32.tf32.f32 "
        "{%0,%1,%2,%3}, {%4,%5,%6,%7}, {%8,%9}, {%0,%1,%2,%3};"
        : "+f"(c[0]), "+f"(c[1]), "+f"(c[2]), "+f"(c[3])
        : "r"(a0), "r"(a1), "r"(a2), "r"(a3), "r"(b0), "r"(b1));
}

// ---------------------------------------------------------------------------
// zero the aggregation scratch (must run every replay)
// ---------------------------------------------------------------------------
__global__ void zero_agg_kernel() {
    int i = blockIdx.x * blockDim.x + threadIdx.x;
    ((float4*)g_agg)[i] = make_float4(0.f, 0.f, 0.f, 0.f);
}

// ---------------------------------------------------------------------------
// Edge kernel (PERSISTENT, tensor-core tf32): 296 blocks x 256 threads.
// Weights staged+converted ONCE per block; each block loops over edge tiles.
// warps = 4 row-tiles(16) x 2 col-halves(32); m16n8k8 tf32 mma both layers.
// Edge indices read directly from gmem (L1-resident stream) - no smem idx.
// ---------------------------------------------------------------------------
#define XST 132
#define WST 72
#define HST 68
#define EDGE_SMEM ((64*XST + 128*WST + 64*WST + 64*HST) * 4)

__global__ void __launch_bounds__(256, 2) edge_kernel(
    const float* __restrict__ h, const int* __restrict__ erow, const int* __restrict__ ecol,
    const float* __restrict__ W1, const float* __restrict__ b1,
    const float* __restrict__ W2, const float* __restrict__ b2,
    float* __restrict__ mij)
{
    extern __shared__ float sm[];
    float* Xs  = sm;                     // 64 x 132
    float* W1s = Xs + 64 * XST;          // 128 x 72
    float* W2s = W1s + 128 * WST;        // 64 x 72
    float* Hs  = W2s + 64 * WST;         // 64 x 68

    const int tid = threadIdx.x;

    // stage W1 [128x72] and W2 [64x72], tf32-rounded -- ONCE per block
#pragma unroll
    for (int i = 0; i < 8; i++) {
        int f = i * 256 + tid;
        int k = f >> 4, c = f & 15;
        float4 v = ((const float4*)W1)[f];
        v.x = tf32r(v.x); v.y = tf32r(v.y); v.z = tf32r(v.z); v.w = tf32r(v.w);
        ((float4*)W1s)[k * 18 + c] = v;
    }
#pragma unroll
    for (int i = 0; i < 4; i++) {
        int f = i * 256 + tid;
        int k = f >> 4, c = f & 15;
        float4 v = ((const float4*)W2)[f];
        v.x = tf32r(v.x); v.y = tf32r(v.y); v.z = tf32r(v.z); v.w = tf32r(v.w);
        ((float4*)W2s)[k * 18 + c] = v;
    }
    __syncthreads();

    const int warp = tid >> 5, lane = tid & 31;
    const int rb  = (warp >> 1) * 16;    // row-tile base
    const int nb0 = (warp & 1) * 32;     // col-half base
    const int g   = lane >> 2, tg = lane & 3;
    const float4* h4 = (const float4*)h;

    // biases are loop-invariant: hoist
    float2 b1v[4], b2v[4];
#pragma unroll
    for (int t = 0; t < 4; t++) {
        int nc = nb0 + t * 8 + 2 * tg;
        b1v[t] = *(const float2*)&b1[nc];
        b2v[t] = *(const float2*)&b2[nc];
    }

    for (int tile = blockIdx.x; tile < NTILES; tile += EDGE_GRID) {
        const int eb = tile * 64;

        // gather X = [h[row] | h[col]], tf32-rounded (direct index LDG)
#pragma unroll
        for (int i = 0; i < 8; i++) {
            int f = i * 256 + tid;
            int r = f >> 5, p = f & 31;
            int node = (p < 16) ? erow[eb + r] : ecol[eb + r];
            float4 v = h4[node * 16 + (p & 15)];
            v.x = tf32r(v.x); v.y = tf32r(v.y); v.z = tf32r(v.z); v.w = tf32r(v.w);
            ((float4*)Xs)[r * 33 + p] = v;
        }
        __syncthreads();

        float acc[4][4];
#pragma unroll
        for (int t = 0; t < 4; t++)
#pragma unroll
            for (int j = 0; j < 4; j++) acc[t][j] = 0.f;

        // layer 1: [64x128] @ [128x64]
        {
            const float* A0 = Xs + (rb + g) * XST + tg;
            const float* A1 = Xs + (rb + g + 8) * XST + tg;
#pragma unroll
            for (int kk = 0; kk < 16; kk++) {
                int k0 = kk * 8;
                uint32_t a0 = __float_as_uint(A0[k0]);
                uint32_t a1 = __float_as_uint(A1[k0]);
                uint32_t a2 = __float_as_uint(A0[k0 + 4]);
                uint32_t a3 = __float_as_uint(A1[k0 + 4]);
                const float* Bp = W1s + (k0 + tg) * WST + nb0 + g;
#pragma unroll
                for (int t = 0; t < 4; t++) {
                    uint32_t b0 = __float_as_uint(Bp[t * 8]);
                    uint32_t bq = __float_as_uint(Bp[t * 8 + 4 * WST]);
                    mma_tf32(acc[t], a0, a1, a2, a3, b0, bq);
                }
            }
        }
        // epilogue 1: bias + silu + tf32 round -> Hs
#pragma unroll
        for (int t = 0; t < 4; t++) {
            int nc = nb0 + t * 8 + 2 * tg;
            float2 v0, v1;
            v0.x = tf32r(silu_f(acc[t][0] + b1v[t].x));
            v0.y = tf32r(silu_f(acc[t][1] + b1v[t].y));
            v1.x = tf32r(silu_f(acc[t][2] + b1v[t].x));
            v1.y = tf32r(silu_f(acc[t][3] + b1v[t].y));
            *(float2*)&Hs[(rb + g) * HST + nc]     = v0;
            *(float2*)&Hs[(rb + g + 8) * HST + nc] = v1;
        }
        __syncthreads();

#pragma unroll
        for (int t = 0; t < 4; t++)
#pragma unroll
            for (int j = 0; j < 4; j++) acc[t][j] = 0.f;

        // layer 2: [64x64] @ [64x64]
        {
            const float* A0 = Hs + (rb + g) * HST + tg;
            const float* A1 = Hs + (rb + g + 8) * HST + tg;
#pragma unroll
            for (int kk = 0; kk < 8; kk++) {
                int k0 = kk * 8;
                uint32_t a0 = __float_as_uint(A0[k0]);
                uint32_t a1 = __float_as_uint(A1[k0]);
                uint32_t a2 = __float_as_uint(A0[k0 + 4]);
                uint32_t a3 = __float_as_uint(A1[k0 + 4]);
                const float* Bp = W2s + (k0 + tg) * WST + nb0 + g;
#pragma unroll
                for (int t = 0; t < 4; t++) {
                    uint32_t b0 = __float_as_uint(Bp[t * 8]);
                    uint32_t bq = __float_as_uint(Bp[t * 8 + 4 * WST]);
                    mma_tf32(acc[t], a0, a1, a2, a3, b0, bq);
                }
            }
        }
        // epilogue 2: bias + silu -> mij (float2) + scatter-add into g_agg
        {
            int row0 = rb + g, row1 = rb + g + 8;
            int nd0 = erow[eb + row0], nd1 = erow[eb + row1];
            size_t ge0 = (size_t)(eb + row0) * 64;
            size_t ge1 = (size_t)(eb + row1) * 64;
#pragma unroll
            for (int t = 0; t < 4; t++) {
                int nc = nb0 + t * 8 + 2 * tg;
                float2 m0, m1;
                m0.x = silu_f(acc[t][0] + b2v[t].x);
                m0.y = silu_f(acc[t][1] + b2v[t].y);
                m1.x = silu_f(acc[t][2] + b2v[t].x);
                m1.y = silu_f(acc[t][3] + b2v[t].y);
                *(float2*)&mij[ge0 + nc] = m0;
                *(float2*)&mij[ge1 + nc] = m1;
                asm volatile("red.global.add.v2.f32 [%0], {%1,%2};"
                             :: "l"(&g_agg[(size_t)nd0 * 64 + nc]), "f"(m0.x), "f"(m0.y) : "memory");
                asm volatile("red.global.add.v2.f32 [%0], {%1,%2};"
                             :: "l"(&g_agg[(size_t)nd1 * 64 + nc]), "f"(m1.x), "f"(m1.y) : "memory");
            }
        }
        __syncthreads();   // protect Xs/Hs before next tile's gather
    }
}

// ---------------------------------------------------------------------------
// 3-qubit statevector circuit (per node, per thread)
// ---------------------------------------------------------------------------
__device__ __forceinline__ void apply_rx3(float* ar, float* ai, float cb, float sb) {
#pragma unroll
    for (int q = 0; q < 3; q++) {
        int st = 4 >> q;
#pragma unroll
        for (int i = 0; i < 8; i++) {
            if (i & st) continue;
            int j = i + st;
            float a0r = ar[i], a0i = ai[i], a1r = ar[j], a1i = ai[j];
            ar[i] =  cb * a0r + sb * a1i;
            ai[i] =  cb * a0i - sb * a1r;
            ar[j] =  sb * a0i + cb * a1r;
            ai[j] = -sb * a0r + cb * a1i;
        }
    }
}

__device__ __forceinline__ void apply_rz(float* ar, float* ai, int st, float theta) {
    float s, c;
    sincosf(0.5f * theta, &s, &c);
#pragma unroll
    for (int i = 0; i < 8; i++) {
        float r = ar[i], im = ai[i];
        if (i & st) { ar[i] = r * c - im * s; ai[i] = im * c + r * s; }
        else        { ar[i] = r * c + im * s; ai[i] = im * c - r * s; }
    }
}

__device__ __forceinline__ void apply_h(float* ar, float* ai, int st) {
    const float SQ = 0.70710678118654752f;
#pragma unroll
    for (int i = 0; i < 8; i++) {
        if (i & st) continue;
        int j = i + st;
        float a0r = ar[i], a0i = ai[i], a1r = ar[j], a1i = ai[j];
        ar[i] = (a0r + a1r) * SQ; ai[i] = (a0i + a1i) * SQ;
        ar[j] = (a0r - a1r) * SQ; ai[j] = (a0i - a1i) * SQ;
    }
}

__device__ void qcircuit(const float* x, float alpha, float beta, float gamma, float delta,
                         const float* __restrict__ Lam, float* outq)
{
    float ar[8], ai[8];
#pragma unroll
    for (int i = 0; i < 8; i++) { ar[i] = 0.f; ai[i] = 0.f; }
    ar[0] = 1.f;

#pragma unroll
    for (int q = 0; q < 3; q++) {
        float s, c;
        sincosf(0.5f * alpha * x[q], &s, &c);
        int st = 4 >> q;
#pragma unroll
        for (int i = 0; i < 8; i++) {
            if (i & st) continue;
            int j = i + st;
            float a0r = ar[i], a0i = ai[i], a1r = ar[j], a1i = ai[j];
            ar[i] = c * a0r - s * a1r; ai[i] = c * a0i - s * a1i;
            ar[j] = s * a0r + c * a1r; ai[j] = s * a0i + c * a1i;
        }
    }
#pragma unroll
    for (int qi = 0; qi < 3; qi++)
#pragma unroll
        for (int qj = qi + 1; qj < 3; qj++) {
            float phi = 0.5f * gamma * (Lam[qi * 3 + qj] + Lam[qj * 3 + qi]);
            float sp, cp;
            sincosf(0.5f * phi, &sp, &cp);
#pragma unroll
            for (int i = 0; i < 8; i++) {
                int bi = (i >> (2 - qi)) & 1, bj = (i >> (2 - qj)) & 1;
                float pi = (bi ^ bj) ? sp : -sp;
                float r = ar[i] * cp - ai[i] * pi;
                ai[i]   = ar[i] * pi + ai[i] * cp;
                ar[i]   = r;
            }
        }
    float sb, cb;
    sincosf(0.5f * beta, &sb, &cb);
    apply_rx3(ar, ai, cb, sb);
#pragma unroll
    for (int q = 0; q < 3; q++) {
        int st = 4 >> q;
        float x2 = x[q] * x[q];
        apply_rz(ar, ai, st, delta * (1.f - 0.5f * x2));
        apply_h(ar, ai, st);
        apply_rz(ar, ai, st, delta * x2);
        apply_h(ar, ai, st);
    }
    apply_rx3(ar, ai, cb, sb);

    float e0 = 0.f, e1 = 0.f, e2 = 0.f;
#pragma unroll
    for (int i = 0; i < 8; i++) {
        float p = ar[i] * ar[i] + ai[i] * ai[i];
        e0 += (i & 4) ? -p : p;
        e1 += (i & 2) ? -p : p;
        e2 += (i & 1) ? -p : p;
    }
    outq[0] = e0; outq[1] = e1; outq[2] = e2;
}

// ---------------------------------------------------------------------------
// Node kernel (tensor-core tf32): 64 nodes/block, 256 threads (8 warps).
// Xs kept fp32 (exact residual + circuit I/O); A-operands cvt-on-load.
// ---------------------------------------------------------------------------
#define NXST 132
#define NWST 72
#define NHST 68
#define NODE_SMEM ((64*NXST + 131*NWST + 64*NHST) * 4)

__global__ void __launch_bounds__(256, 2) node_kernel(
    const float* __restrict__ h,
    const float* __restrict__ qW1, const float* __restrict__ qb1,
    const float* __restrict__ qW2, const float* __restrict__ qb2,
    const float* __restrict__ pW1, const float* __restrict__ pb1,
    const float* __restrict__ pW2, const float* __restrict__ pb2,
    const float* __restrict__ alpha_p, const float* __restrict__ beta_p,
    const float* __restrict__ gamma_p, const float* __restrict__ delta_p,
    const float* __restrict__ Lam,
    float* __restrict__ out)
{
    extern __shared__ float sm[];
    float* Xs = sm;                 // 64 x 132 fp32: [h(64) | agg/100(64) | q_out(3) | pad]
    float* Ws = Xs + 64 * NXST;     // up to 131 x 72 (tf32-rounded weights)
    float* Hs = Ws + 131 * NWST;    // 64 x 68

    const int tid = threadIdx.x;
    const int nb  = blockIdx.x * 64;

    // gather X (fp32, unrounded)
    const float4* h4 = (const float4*)h;
    const float4* a4 = (const float4*)g_agg;
#pragma unroll
    for (int i = 0; i < 8; i++) {
        int f = i * 256 + tid;
        int r = f >> 5, p = f & 31;
        int node = nb + r;
        float4 v = make_float4(0.f, 0.f, 0.f, 0.f);
        if (node < NN) {
            if (p < 16) v = h4[node * 16 + p];
            else {
                v = a4[node * 16 + (p - 16)];
                v.x *= 0.01f; v.y *= 0.01f; v.z *= 0.01f; v.w *= 0.01f;
            }
        }
        ((float4*)Xs)[r * 33 + p] = v;
    }
    if (tid < 64) ((float4*)Xs)[tid * 33 + 32] = make_float4(0.f, 0.f, 0.f, 0.f);

    // stage qW1 [128x72], tf32-rounded
#pragma unroll
    for (int i = 0; i < 8; i++) {
        int f = i * 256 + tid;
        int k = f >> 4, c = f & 15;
        float4 v = ((const float4*)qW1)[f];
        v.x = tf32r(v.x); v.y = tf32r(v.y); v.z = tf32r(v.z); v.w = tf32r(v.w);
        ((float4*)Ws)[k * 18 + c] = v;
    }
    __syncthreads();

    const int warp = tid >> 5, lane = tid & 31;
    const int rb  = (warp >> 1) * 16;
    const int nb0 = (warp & 1) * 32;
    const int g   = lane >> 2, tg = lane & 3;

    float acc[4][4];
#pragma unroll
    for (int t = 0; t < 4; t++)
#pragma unroll
        for (int j = 0; j < 4; j++) acc[t][j] = 0.f;

    // phase A: H = silu(X[:, :128] @ qW1 + qb1)
    {
        const float* A0 = Xs + (rb + g) * NXST + tg;
        const float* A1 = Xs + (rb + g + 8) * NXST + tg;
#pragma unroll
        for (int kk = 0; kk < 16; kk++) {
            int k0 = kk * 8;
            uint32_t a0 = tf32u(A0[k0]);
            uint32_t a1 = tf32u(A1[k0]);
            uint32_t a2 = tf32u(A0[k0 + 4]);
            uint32_t a3 = tf32u(A1[k0 + 4]);
            const float* Bp = Ws + (k0 + tg) * NWST + nb0 + g;
#pragma unroll
            for (int t = 0; t < 4; t++) {
                uint32_t b0 = __float_as_uint(Bp[t * 8]);
                uint32_t bq = __float_as_uint(Bp[t * 8 + 4 * NWST]);
                mma_tf32(acc[t], a0, a1, a2, a3, b0, bq);
            }
        }
    }
#pragma unroll
    for (int t = 0; t < 4; t++) {
        int nc = nb0 + t * 8 + 2 * tg;
        float2 bb = *(const float2*)&qb1[nc];
        float2 v0, v1;
        v0.x = silu_f(acc[t][0] + bb.x);
        v0.y = silu_f(acc[t][1] + bb.y);
        v1.x = silu_f(acc[t][2] + bb.x);
        v1.y = silu_f(acc[t][3] + bb.y);
        *(float2*)&Hs[(rb + g) * NHST + nc]     = v0;
        *(float2*)&Hs[(rb + g + 8) * NHST + nc] = v1;
    }
    __syncthreads();

    // phase B: q_in = H @ qW2 + qb2 ; quantum circuit (one thread per node)
    if (tid < 64) {
        float qin[3] = { qb2[0], qb2[1], qb2[2] };
        for (int k = 0; k < 64; k++) {
            float hv = Hs[tid * NHST + k];
            qin[0] += hv * qW2[k * 3 + 0];
            qin[1] += hv * qW2[k * 3 + 1];
            qin[2] += hv * qW2[k * 3 + 2];
        }
        float qo[3];
        qcircuit(qin, *alpha_p, *beta_p, *gamma_p, *delta_p, Lam, qo);
        Xs[tid * NXST + 128] = qo[0];
        Xs[tid * NXST + 129] = qo[1];
        Xs[tid * NXST + 130] = qo[2];
    }
    __syncthreads();

    // stage pW1 [131x72], tf32-rounded
    for (int f = tid; f < 131 * 16; f += 256) {
        int k = f >> 4, c = f & 15;
        float4 v = ((const float4*)pW1)[f];
        v.x = tf32r(v.x); v.y = tf32r(v.y); v.z = tf32r(v.z); v.w = tf32r(v.w);
        ((float4*)Ws)[k * 18 + c] = v;
    }
    __syncthreads();

    // phase C: P = silu(X[:, :131] @ pW1 + pb1)  (MMA k=0..127 + fp32 tail)
#pragma unroll
    for (int t = 0; t < 4; t++)
#pragma unroll
        for (int j = 0; j < 4; j++) acc[t][j] = 0.f;
    {
        const float* A0 = Xs + (rb + g) * NXST + tg;
        const float* A1 = Xs + (rb + g + 8) * NXST + tg;
#pragma unroll
        for (int kk = 0; kk < 16; kk++) {
            int k0 = kk * 8;
            uint32_t a0 = tf32u(A0[k0]);
            uint32_t a1 = tf32u(A1[k0]);
            uint32_t a2 = tf32u(A0[k0 + 4]);
            uint32_t a3 = tf32u(A1[k0 + 4]);
            const float* Bp = Ws + (k0 + tg) * NWST + nb0 + g;
#pragma unroll
            for (int t = 0; t < 4; t++) {
                uint32_t b0 = __float_as_uint(Bp[t * 8]);
                uint32_t bq = __float_as_uint(Bp[t * 8 + 4 * NWST]);
                mma_tf32(acc[t], a0, a1, a2, a3, b0, bq);
            }
        }
        // fp32 tail k = 128..130 (q_out columns)
#pragma unroll
        for (int k = 128; k < 131; k++) {
            float xa = Xs[(rb + g) * NXST + k];
            float xb = Xs[(rb + g + 8) * NXST + k];
#pragma unroll
            for (int t = 0; t < 4; t++) {
                int nc = nb0 + t * 8 + 2 * tg;
                float w0 = Ws[k * NWST + nc];
                float w1 = Ws[k * NWST + nc + 1];
                acc[t][0] += xa * w0; acc[t][1] += xa * w1;
                acc[t][2] += xb * w0; acc[t][3] += xb * w1;
            }
        }
    }
#pragma unroll
    for (int t = 0; t < 4; t++) {
        int nc = nb0 + t * 8 + 2 * tg;
        float2 bb = *(const float2*)&pb1[nc];
        float2 v0, v1;
        v0.x = tf32r(silu_f(acc[t][0] + bb.x));
        v0.y = tf32r(silu_f(acc[t][1] + bb.y));
        v1.x = tf32r(silu_f(acc[t][2] + bb.x));
        v1.y = tf32r(silu_f(acc[t][3] + bb.y));
        *(float2*)&Hs[(rb + g) * NHST + nc]     = v0;
        *(float2*)&Hs[(rb + g + 8) * NHST + nc] = v1;
    }
    __syncthreads();

    // stage pW2 [64x72], tf32-rounded
    for (int f = tid; f < 64 * 16; f += 256) {
        int k = f >> 4, c = f & 15;
        float4 v = ((const float4*)pW2)[f];
        v.x = tf32r(v.x); v.y = tf32r(v.y); v.z = tf32r(v.z); v.w = tf32r(v.w);
        ((float4*)Ws)[k * 18 + c] = v;
    }
    __syncthreads();

    // phase D: out = h + P @ pW2 + pb2
#pragma unroll
    for (int t = 0; t < 4; t++)
#pragma unroll
        for (int j = 0; j < 4; j++) acc[t][j] = 0.f;
    {
        const float* A0 = Hs + (rb + g) * NHST + tg;
        const float* A1 = Hs + (rb + g + 8) * NHST + tg;
#pragma unroll
        for (int kk = 0; kk < 8; kk++) {
            int k0 = kk * 8;
            uint32_t a0 = __float_as_uint(A0[k0]);
            uint32_t a1 = __float_as_uint(A1[k0]);
            uint32_t a2 = __float_as_uint(A0[k0 + 4]);
            uint32_t a3 = __float_as_uint(A1[k0 + 4]);
            const float* Bp = Ws + (k0 + tg) * NWST + nb0 + g;
#pragma unroll
            for (int t = 0; t < 4; t++) {
                uint32_t b0 = __float_as_uint(Bp[t * 8]);
                uint32_t bq = __float_as_uint(Bp[t * 8 + 4 * NWST]);
                mma_tf32(acc[t], a0, a1, a2, a3, b0, bq);
            }
        }
    }
    {
        int row0 = rb + g, row1 = rb + g + 8;
        int n0 = nb + row0, n1 = nb + row1;
#pragma unroll
        for (int t = 0; t < 4; t++) {
            int nc = nb0 + t * 8 + 2 * tg;
            float2 bb = *(const float2*)&pb2[nc];
            if (n0 < NN) {
                float2 v;
                v.x = Xs[row0 * NXST + nc]     + acc[t][0] + bb.x;
                v.y = Xs[row0 * NXST + nc + 1] + acc[t][1] + bb.y;
                *(float2*)&out[(size_t)n0 * 64 + nc] = v;
            }
            if (n1 < NN) {
                float2 v;
                v.x = Xs[row1 * NXST + nc]     + acc[t][2] + bb.x;
                v.y = Xs[row1 * NXST + nc + 1] + acc[t][3] + bb.y;
                *(float2*)&out[(size_t)n1 * 64 + nc] = v;
            }
        }
    }
}

// ---------------------------------------------------------------------------
extern "C" void kernel_launch(void* const* d_in, const int* in_sizes, int n_in,
                              void* d_out, int out_size) {
    const float* h   = (const float*)d_in[0];
    const int*   ei  = (const int*)d_in[1];
    const float* eW1 = (const float*)d_in[2];
    const float* eb1 = (const float*)d_in[3];
    const float* eW2 = (const float*)d_in[4];
    const float* eb2 = (const float*)d_in[5];
    const float* qW1 = (const float*)d_in[6];
    const float* qb1 = (const float*)d_in[7];
    const float* qW2 = (const float*)d_in[8];
    const float* qb2 = (const float*)d_in[9];
    const float* pW1 = (const float*)d_in[10];
    const float* pb1 = (const float*)d_in[11];
    const float* pW2 = (const float*)d_in[12];
    const float* pb2 = (const float*)d_in[13];
    const float* al  = (const float*)d_in[14];
    const float* be  = (const float*)d_in[15];
    const float* ga  = (const float*)d_in[16];
    const float* de  = (const float*)d_in[17];
    const float* Lam = (const float*)d_in[18];

    float* out = (float*)d_out;
    float* mij = out + (size_t)NN * DD;

    cudaFuncSetAttribute(edge_kernel, cudaFuncAttributeMaxDynamicSharedMemorySize, EDGE_SMEM);
    cudaFuncSetAttribute(node_kernel, cudaFuncAttributeMaxDynamicSharedMemorySize, NODE_SMEM);

    zero_agg_kernel<<<(NN * DD / 4) / 256, 256>>>();
    edge_kernel<<<EDGE_GRID, 256, EDGE_SMEM>>>(h, ei, ei + NE, eW1, eb1, eW2, eb2, mij);
    node_kernel<<<(NN + 63) / 64, 256, NODE_SMEM>>>(h, qW1, qb1, qW2, qb2,
                                                    pW1, pb1, pW2, pb2,
                                                    al, be, ga, de, Lam, out);
}

// round 16
// speedup vs baseline: 2.8995x; 1.0142x over previous
#include <cuda_runtime.h>
#include <cstdint>

#define NN  50000
#define NE  800000
#define DD  64
#define HID 64
#define NTILES (NE / 64)
#define EDGE_GRID 296

// Scratch: aggregation buffer (allocation-free rule -> __device__ global)
__device__ float g_agg[NN * DD];

__device__ __forceinline__ float silu_f(float v) {
    return v * (1.0f / (1.0f + __expf(-v)));
}

// round fp32 -> tf32 (rna); value kept in a 32-bit float slot
__device__ __forceinline__ float tf32r(float x) {
    uint32_t u;
    asm("cvt.rna.tf32.f32 %0, %1;" : "=r"(u) : "f"(x));
    return __uint_as_float(u);
}
// round fp32 -> tf32 bits
__device__ __forceinline__ uint32_t tf32u(float x) {
    uint32_t u;
    asm("cvt.rna.tf32.f32 %0, %1;" : "=r"(u) : "f"(x));
    return u;
}

// m16n8k8 tf32 MMA, fp32 accumulate
__device__ __forceinline__ void mma_tf32(float* c,
    uint32_t a0, uint32_t a1, uint32_t a2, uint32_t a3,
    uint32_t b0, uint32_t b1)
{
    asm volatile(
        "mma.sync.aligned.m16n8k8.row.col.f32.tf32.tf32.f32 "
        "{%0,%1,%2,%3}, {%4,%5,%6,%7}, {%8,%9}, {%0,%1,%2,%3};"
        : "+f"(c[0]), "+f"(c[1]), "+f"(c[2]), "+f"(c[3])
        : "r"(a0), "r"(a1), "r"(a2), "r"(a3), "r"(b0), "r"(b1));
}

// ---------------------------------------------------------------------------
// zero the aggregation scratch (must run every replay)
// ---------------------------------------------------------------------------
__global__ void zero_agg_kernel() {
    int i = blockIdx.x * blockDim.x + threadIdx.x;
    ((float4*)g_agg)[i] = make_float4(0.f, 0.f, 0.f, 0.f);
}

// ---------------------------------------------------------------------------
// Edge kernel (PERSISTENT + register-pipelined gather, tf32 tensor cores):
// 296 blocks x 256 threads; weights staged once; each block loops over tiles.
// Next tile's X gather (LDG) issued right after tile-top sync -> latency
// hidden behind layer1+layer2 compute. 2 syncs per tile.
// ---------------------------------------------------------------------------
#define XST 132
#define WST 72
#define HST 68
#define EDGE_SMEM ((64*XST + 128*WST + 64*WST + 64*HST) * 4)

__global__ void __launch_bounds__(256, 2) edge_kernel(
    const float* __restrict__ h, const int* __restrict__ erow, const int* __restrict__ ecol,
    const float* __restrict__ W1, const float* __restrict__ b1,
    const float* __restrict__ W2, const float* __restrict__ b2,
    float* __restrict__ mij)
{
    extern __shared__ float sm[];
    float* Xs  = sm;                     // 64 x 132
    float* W1s = Xs + 64 * XST;          // 128 x 72
    float* W2s = W1s + 128 * WST;        // 64 x 72
    float* Hs  = W2s + 64 * WST;         // 64 x 68

    const int tid = threadIdx.x;

    // stage W1 [128x72] and W2 [64x72], tf32-rounded -- ONCE per block
#pragma unroll
    for (int i = 0; i < 8; i++) {
        int f = i * 256 + tid;
        int k = f >> 4, c = f & 15;
        float4 v = ((const float4*)W1)[f];
        v.x = tf32r(v.x); v.y = tf32r(v.y); v.z = tf32r(v.z); v.w = tf32r(v.w);
        ((float4*)W1s)[k * 18 + c] = v;
    }
#pragma unroll
    for (int i = 0; i < 4; i++) {
        int f = i * 256 + tid;
        int k = f >> 4, c = f & 15;
        float4 v = ((const float4*)W2)[f];
        v.x = tf32r(v.x); v.y = tf32r(v.y); v.z = tf32r(v.z); v.w = tf32r(v.w);
        ((float4*)W2s)[k * 18 + c] = v;
    }
    // (sync below, before first tile's STS consumers)

    const int warp = tid >> 5, lane = tid & 31;
    const int rb  = (warp >> 1) * 16;    // row-tile base
    const int nb0 = (warp & 1) * 32;     // col-half base
    const int g   = lane >> 2, tg = lane & 3;
    const float4* h4 = (const float4*)h;

    // biases are loop-invariant: hoist
    float2 b1v[4], b2v[4];
#pragma unroll
    for (int t = 0; t < 4; t++) {
        int nc = nb0 + t * 8 + 2 * tg;
        b1v[t] = *(const float2*)&b1[nc];
        b2v[t] = *(const float2*)&b2[nc];
    }

    // per-thread gather geometry (fixed across tiles)
    int grow[8], gpos[8];
#pragma unroll
    for (int i = 0; i < 8; i++) {
        int f = i * 256 + tid;
        grow[i] = f >> 5;        // tile-local edge row 0..63
        gpos[i] = f & 31;        // float4 slot within 128-float row
    }

    // prefetch first tile into registers
    float4 pf[8];
    int tile = blockIdx.x;
    if (tile < NTILES) {
        int eb = tile * 64;
#pragma unroll
        for (int i = 0; i < 8; i++) {
            int node = (gpos[i] < 16) ? erow[eb + grow[i]] : ecol[eb + grow[i]];
            pf[i] = h4[node * 16 + (gpos[i] & 15)];
        }
    }
    __syncthreads();   // weights staged (and Xs not yet touched)

    for (; tile < NTILES; tile += EDGE_GRID) {
        // store prefetched X (tf32-rounded) -> Xs
#pragma unroll
        for (int i = 0; i < 8; i++) {
            float4 v = pf[i];
            v.x = tf32r(v.x); v.y = tf32r(v.y); v.z = tf32r(v.z); v.w = tf32r(v.w);
            ((float4*)Xs)[grow[i] * 33 + gpos[i]] = v;
        }
        __syncthreads();   // Xs ready; prev iter's Hs reads all done

        // issue prefetch for next tile (latency hidden behind both layers)
        int nt = tile + EDGE_GRID;
        if (nt < NTILES) {
            int eb2 = nt * 64;
#pragma unroll
            for (int i = 0; i < 8; i++) {
                int node = (gpos[i] < 16) ? erow[eb2 + grow[i]] : ecol[eb2 + grow[i]];
                pf[i] = h4[node * 16 + (gpos[i] & 15)];
            }
        }

        float acc[4][4];
#pragma unroll
        for (int t = 0; t < 4; t++)
#pragma unroll
            for (int j = 0; j < 4; j++) acc[t][j] = 0.f;

        // layer 1: [64x128] @ [128x64]
        {
            const float* A0 = Xs + (rb + g) * XST + tg;
            const float* A1 = Xs + (rb + g + 8) * XST + tg;
#pragma unroll
            for (int kk = 0; kk < 16; kk++) {
                int k0 = kk * 8;
                uint32_t a0 = __float_as_uint(A0[k0]);
                uint32_t a1 = __float_as_uint(A1[k0]);
                uint32_t a2 = __float_as_uint(A0[k0 + 4]);
                uint32_t a3 = __float_as_uint(A1[k0 + 4]);
                const float* Bp = W1s + (k0 + tg) * WST + nb0 + g;
#pragma unroll
                for (int t = 0; t < 4; t++) {
                    uint32_t b0 = __float_as_uint(Bp[t * 8]);
                    uint32_t bq = __float_as_uint(Bp[t * 8 + 4 * WST]);
                    mma_tf32(acc[t], a0, a1, a2, a3, b0, bq);
                }
            }
        }
        // epilogue 1: bias + silu + tf32 round -> Hs
#pragma unroll
        for (int t = 0; t < 4; t++) {
            int nc = nb0 + t * 8 + 2 * tg;
            float2 v0, v1;
            v0.x = tf32r(silu_f(acc[t][0] + b1v[t].x));
            v0.y = tf32r(silu_f(acc[t][1] + b1v[t].y));
            v1.x = tf32r(silu_f(acc[t][2] + b1v[t].x));
            v1.y = tf32r(silu_f(acc[t][3] + b1v[t].y));
            *(float2*)&Hs[(rb + g) * HST + nc]     = v0;
            *(float2*)&Hs[(rb + g + 8) * HST + nc] = v1;
        }
        __syncthreads();   // Hs ready; Xs free for next iter's STS

#pragma unroll
        for (int t = 0; t < 4; t++)
#pragma unroll
            for (int j = 0; j < 4; j++) acc[t][j] = 0.f;

        // layer 2: [64x64] @ [64x64]
        {
            const float* A0 = Hs + (rb + g) * HST + tg;
            const float* A1 = Hs + (rb + g + 8) * HST + tg;
#pragma unroll
            for (int kk = 0; kk < 8; kk++) {
                int k0 = kk * 8;
                uint32_t a0 = __float_as_uint(A0[k0]);
                uint32_t a1 = __float_as_uint(A1[k0]);
                uint32_t a2 = __float_as_uint(A0[k0 + 4]);
                uint32_t a3 = __float_as_uint(A1[k0 + 4]);
                const float* Bp = W2s + (k0 + tg) * WST + nb0 + g;
#pragma unroll
                for (int t = 0; t < 4; t++) {
                    uint32_t b0 = __float_as_uint(Bp[t * 8]);
                    uint32_t bq = __float_as_uint(Bp[t * 8 + 4 * WST]);
                    mma_tf32(acc[t], a0, a1, a2, a3, b0, bq);
                }
            }
        }
        // epilogue 2: bias + silu -> mij (float2) + scatter-add into g_agg
        {
            int eb = tile * 64;
            int row0 = rb + g, row1 = rb + g + 8;
            int nd0 = erow[eb + row0], nd1 = erow[eb + row1];
            size_t ge0 = (size_t)(eb + row0) * 64;
            size_t ge1 = (size_t)(eb + row1) * 64;
#pragma unroll
            for (int t = 0; t < 4; t++) {
                int nc = nb0 + t * 8 + 2 * tg;
                float2 m0, m1;
                m0.x = silu_f(acc[t][0] + b2v[t].x);
                m0.y = silu_f(acc[t][1] + b2v[t].y);
                m1.x = silu_f(acc[t][2] + b2v[t].x);
                m1.y = silu_f(acc[t][3] + b2v[t].y);
                *(float2*)&mij[ge0 + nc] = m0;
                *(float2*)&mij[ge1 + nc] = m1;
                asm volatile("red.global.add.v2.f32 [%0], {%1,%2};"
                             :: "l"(&g_agg[(size_t)nd0 * 64 + nc]), "f"(m0.x), "f"(m0.y) : "memory");
                asm volatile("red.global.add.v2.f32 [%0], {%1,%2};"
                             :: "l"(&g_agg[(size_t)nd1 * 64 + nc]), "f"(m1.x), "f"(m1.y) : "memory");
            }
        }
        // no sync here: next iter's STS->Xs is safe (all warps past layer1 via
        // mid-sync); Hs overwrite is gated by next iter's top sync.
    }
}

// ---------------------------------------------------------------------------
// 3-qubit statevector circuit (per node, per thread)
// ---------------------------------------------------------------------------
__device__ __forceinline__ void apply_rx3(float* ar, float* ai, float cb, float sb) {
#pragma unroll
    for (int q = 0; q < 3; q++) {
        int st = 4 >> q;
#pragma unroll
        for (int i = 0; i < 8; i++) {
            if (i & st) continue;
            int j = i + st;
            float a0r = ar[i], a0i = ai[i], a1r = ar[j], a1i = ai[j];
            ar[i] =  cb * a0r + sb * a1i;
            ai[i] =  cb * a0i - sb * a1r;
            ar[j] =  sb * a0i + cb * a1r;
            ai[j] = -sb * a0r + cb * a1i;
        }
    }
}

__device__ __forceinline__ void apply_rz(float* ar, float* ai, int st, float theta) {
    float s, c;
    sincosf(0.5f * theta, &s, &c);
#pragma unroll
    for (int i = 0; i < 8; i++) {
        float r = ar[i], im = ai[i];
        if (i & st) { ar[i] = r * c - im * s; ai[i] = im * c + r * s; }
        else        { ar[i] = r * c + im * s; ai[i] = im * c - r * s; }
    }
}

__device__ __forceinline__ void apply_h(float* ar, float* ai, int st) {
    const float SQ = 0.70710678118654752f;
#pragma unroll
    for (int i = 0; i < 8; i++) {
        if (i & st) continue;
        int j = i + st;
        float a0r = ar[i], a0i = ai[i], a1r = ar[j], a1i = ai[j];
        ar[i] = (a0r + a1r) * SQ; ai[i] = (a0i + a1i) * SQ;
        ar[j] = (a0r - a1r) * SQ; ai[j] = (a0i - a1i) * SQ;
    }
}

__device__ void qcircuit(const float* x, float alpha, float beta, float gamma, float delta,
                         const float* __restrict__ Lam, float* outq)
{
    float ar[8], ai[8];
#pragma unroll
    for (int i = 0; i < 8; i++) { ar[i] = 0.f; ai[i] = 0.f; }
    ar[0] = 1.f;

#pragma unroll
    for (int q = 0; q < 3; q++) {
        float s, c;
        sincosf(0.5f * alpha * x[q], &s, &c);
        int st = 4 >> q;
#pragma unroll
        for (int i = 0; i < 8; i++) {
            if (i & st) continue;
            int j = i + st;
            float a0r = ar[i], a0i = ai[i], a1r = ar[j], a1i = ai[j];
            ar[i] = c * a0r - s * a1r; ai[i] = c * a0i - s * a1i;
            ar[j] = s * a0r + c * a1r; ai[j] = s * a0i + c * a1i;
        }
    }
#pragma unroll
    for (int qi = 0; qi < 3; qi++)
#pragma unroll
        for (int qj = qi + 1; qj < 3; qj++) {
            float phi = 0.5f * gamma * (Lam[qi * 3 + qj] + Lam[qj * 3 + qi]);
            float sp, cp;
            sincosf(0.5f * phi, &sp, &cp);
#pragma unroll
            for (int i = 0; i < 8; i++) {
                int bi = (i >> (2 - qi)) & 1, bj = (i >> (2 - qj)) & 1;
                float pi = (bi ^ bj) ? sp : -sp;
                float r = ar[i] * cp - ai[i] * pi;
                ai[i]   = ar[i] * pi + ai[i] * cp;
                ar[i]   = r;
            }
        }
    float sb, cb;
    sincosf(0.5f * beta, &sb, &cb);
    apply_rx3(ar, ai, cb, sb);
#pragma unroll
    for (int q = 0; q < 3; q++) {
        int st = 4 >> q;
        float x2 = x[q] * x[q];
        apply_rz(ar, ai, st, delta * (1.f - 0.5f * x2));
        apply_h(ar, ai, st);
        apply_rz(ar, ai, st, delta * x2);
        apply_h(ar, ai, st);
    }
    apply_rx3(ar, ai, cb, sb);

    float e0 = 0.f, e1 = 0.f, e2 = 0.f;
#pragma unroll
    for (int i = 0; i < 8; i++) {
        float p = ar[i] * ar[i] + ai[i] * ai[i];
        e0 += (i & 4) ? -p : p;
        e1 += (i & 2) ? -p : p;
        e2 += (i & 1) ? -p : p;
    }
    outq[0] = e0; outq[1] = e1; outq[2] = e2;
}

// ---------------------------------------------------------------------------
// Node kernel (tensor-core tf32): 64 nodes/block, 256 threads (8 warps).
// Xs kept fp32 (exact residual + circuit I/O); A-operands cvt-on-load.
// ---------------------------------------------------------------------------
#define NXST 132
#define NWST 72
#define NHST 68
#define NODE_SMEM ((64*NXST + 131*NWST + 64*NHST) * 4)

__global__ void __launch_bounds__(256, 2) node_kernel(
    const float* __restrict__ h,
    const float* __restrict__ qW1, const float* __restrict__ qb1,
    const float* __restrict__ qW2, const float* __restrict__ qb2,
    const float* __restrict__ pW1, const float* __restrict__ pb1,
    const float* __restrict__ pW2, const float* __restrict__ pb2,
    const float* __restrict__ alpha_p, const float* __restrict__ beta_p,
    const float* __restrict__ gamma_p, const float* __restrict__ delta_p,
    const float* __restrict__ Lam,
    float* __restrict__ out)
{
    extern __shared__ float sm[];
    float* Xs = sm;                 // 64 x 132 fp32: [h(64) | agg/100(64) | q_out(3) | pad]
    float* Ws = Xs + 64 * NXST;     // up to 131 x 72 (tf32-rounded weights)
    float* Hs = Ws + 131 * NWST;    // 64 x 68

    const int tid = threadIdx.x;
    const int nb  = blockIdx.x * 64;

    // gather X (fp32, unrounded)
    const float4* h4 = (const float4*)h;
    const float4* a4 = (const float4*)g_agg;
#pragma unroll
    for (int i = 0; i < 8; i++) {
        int f = i * 256 + tid;
        int r = f >> 5, p = f & 31;
        int node = nb + r;
        float4 v = make_float4(0.f, 0.f, 0.f, 0.f);
        if (node < NN) {
            if (p < 16) v = h4[node * 16 + p];
            else {
                v = a4[node * 16 + (p - 16)];
                v.x *= 0.01f; v.y *= 0.01f; v.z *= 0.01f; v.w *= 0.01f;
            }
        }
        ((float4*)Xs)[r * 33 + p] = v;
    }
    if (tid < 64) ((float4*)Xs)[tid * 33 + 32] = make_float4(0.f, 0.f, 0.f, 0.f);

    // stage qW1 [128x72], tf32-rounded
#pragma unroll
    for (int i = 0; i < 8; i++) {
        int f = i * 256 + tid;
        int k = f >> 4, c = f & 15;
        float4 v = ((const float4*)qW1)[f];
        v.x = tf32r(v.x); v.y = tf32r(v.y); v.z = tf32r(v.z); v.w = tf32r(v.w);
        ((float4*)Ws)[k * 18 + c] = v;
    }
    __syncthreads();

    const int warp = tid >> 5, lane = tid & 31;
    const int rb  = (warp >> 1) * 16;
    const int nb0 = (warp & 1) * 32;
    const int g   = lane >> 2, tg = lane & 3;

    float acc[4][4];
#pragma unroll
    for (int t = 0; t < 4; t++)
#pragma unroll
        for (int j = 0; j < 4; j++) acc[t][j] = 0.f;

    // phase A: H = silu(X[:, :128] @ qW1 + qb1)
    {
        const float* A0 = Xs + (rb + g) * NXST + tg;
        const float* A1 = Xs + (rb + g + 8) * NXST + tg;
#pragma unroll
        for (int kk = 0; kk < 16; kk++) {
            int k0 = kk * 8;
            uint32_t a0 = tf32u(A0[k0]);
            uint32_t a1 = tf32u(A1[k0]);
            uint32_t a2 = tf32u(A0[k0 + 4]);
            uint32_t a3 = tf32u(A1[k0 + 4]);
            const float* Bp = Ws + (k0 + tg) * NWST + nb0 + g;
#pragma unroll
            for (int t = 0; t < 4; t++) {
                uint32_t b0 = __float_as_uint(Bp[t * 8]);
                uint32_t bq = __float_as_uint(Bp[t * 8 + 4 * NWST]);
                mma_tf32(acc[t], a0, a1, a2, a3, b0, bq);
            }
        }
    }
#pragma unroll
    for (int t = 0; t < 4; t++) {
        int nc = nb0 + t * 8 + 2 * tg;
        float2 bb = *(const float2*)&qb1[nc];
        float2 v0, v1;
        v0.x = silu_f(acc[t][0] + bb.x);
        v0.y = silu_f(acc[t][1] + bb.y);
        v1.x = silu_f(acc[t][2] + bb.x);
        v1.y = silu_f(acc[t][3] + bb.y);
        *(float2*)&Hs[(rb + g) * NHST + nc]     = v0;
        *(float2*)&Hs[(rb + g + 8) * NHST + nc] = v1;
    }
    __syncthreads();

    // phase B: q_in = H @ qW2 + qb2 ; quantum circuit (one thread per node)
    if (tid < 64) {
        float qin[3] = { qb2[0], qb2[1], qb2[2] };
        for (int k = 0; k < 64; k++) {
            float hv = Hs[tid * NHST + k];
            qin[0] += hv * qW2[k * 3 + 0];
            qin[1] += hv * qW2[k * 3 + 1];
            qin[2] += hv * qW2[k * 3 + 2];
        }
        float qo[3];
        qcircuit(qin, *alpha_p, *beta_p, *gamma_p, *delta_p, Lam, qo);
        Xs[tid * NXST + 128] = qo[0];
        Xs[tid * NXST + 129] = qo[1];
        Xs[tid * NXST + 130] = qo[2];
    }
    __syncthreads();

    // stage pW1 [131x72], tf32-rounded
    for (int f = tid; f < 131 * 16; f += 256) {
        int k = f >> 4, c = f & 15;
        float4 v = ((const float4*)pW1)[f];
        v.x = tf32r(v.x); v.y = tf32r(v.y); v.z = tf32r(v.z); v.w = tf32r(v.w);
        ((float4*)Ws)[k * 18 + c] = v;
    }
    __syncthreads();

    // phase C: P = silu(X[:, :131] @ pW1 + pb1)  (MMA k=0..127 + fp32 tail)
#pragma unroll
    for (int t = 0; t < 4; t++)
#pragma unroll
        for (int j = 0; j < 4; j++) acc[t][j] = 0.f;
    {
        const float* A0 = Xs + (rb + g) * NXST + tg;
        const float* A1 = Xs + (rb + g + 8) * NXST + tg;
#pragma unroll
        for (int kk = 0; kk < 16; kk++) {
            int k0 = kk * 8;
            uint32_t a0 = tf32u(A0[k0]);
            uint32_t a1 = tf32u(A1[k0]);
            uint32_t a2 = tf32u(A0[k0 + 4]);
            uint32_t a3 = tf32u(A1[k0 + 4]);
            const float* Bp = Ws + (k0 + tg) * NWST + nb0 + g;
#pragma unroll
            for (int t = 0; t < 4; t++) {
                uint32_t b0 = __float_as_uint(Bp[t * 8]);
                uint32_t bq = __float_as_uint(Bp[t * 8 + 4 * NWST]);
                mma_tf32(acc[t], a0, a1, a2, a3, b0, bq);
            }
        }
        // fp32 tail k = 128..130 (q_out columns)
#pragma unroll
        for (int k = 128; k < 131; k++) {
            float xa = Xs[(rb + g) * NXST + k];
            float xb = Xs[(rb + g + 8) * NXST + k];
#pragma unroll
            for (int t = 0; t < 4; t++) {
                int nc = nb0 + t * 8 + 2 * tg;
                float w0 = Ws[k * NWST + nc];
                float w1 = Ws[k * NWST + nc + 1];
                acc[t][0] += xa * w0; acc[t][1] += xa * w1;
                acc[t][2] += xb * w0; acc[t][3] += xb * w1;
            }
        }
    }
#pragma unroll
    for (int t = 0; t < 4; t++) {
        int nc = nb0 + t * 8 + 2 * tg;
        float2 bb = *(const float2*)&pb1[nc];
        float2 v0, v1;
        v0.x = tf32r(silu_f(acc[t][0] + bb.x));
        v0.y = tf32r(silu_f(acc[t][1] + bb.y));
        v1.x = tf32r(silu_f(acc[t][2] + bb.x));
        v1.y = tf32r(silu_f(acc[t][3] + bb.y));
        *(float2*)&Hs[(rb + g) * NHST + nc]     = v0;
        *(float2*)&Hs[(rb + g + 8) * NHST + nc] = v1;
    }
    __syncthreads();

    // stage pW2 [64x72], tf32-rounded
    for (int f = tid; f < 64 * 16; f += 256) {
        int k = f >> 4, c = f & 15;
        float4 v = ((const float4*)pW2)[f];
        v.x = tf32r(v.x); v.y = tf32r(v.y); v.z = tf32r(v.z); v.w = tf32r(v.w);
        ((float4*)Ws)[k * 18 + c] = v;
    }
    __syncthreads();

    // phase D: out = h + P @ pW2 + pb2
#pragma unroll
    for (int t = 0; t < 4; t++)
#pragma unroll
        for (int j = 0; j < 4; j++) acc[t][j] = 0.f;
    {
        const float* A0 = Hs + (rb + g) * NHST + tg;
        const float* A1 = Hs + (rb + g + 8) * NHST + tg;
#pragma unroll
        for (int kk = 0; kk < 8; kk++) {
            int k0 = kk * 8;
            uint32_t a0 = __float_as_uint(A0[k0]);
            uint32_t a1 = __float_as_uint(A1[k0]);
            uint32_t a2 = __float_as_uint(A0[k0 + 4]);
            uint32_t a3 = __float_as_uint(A1[k0 + 4]);
            const float* Bp = Ws + (k0 + tg) * NWST + nb0 + g;
#pragma unroll
            for (int t = 0; t < 4; t++) {
                uint32_t b0 = __float_as_uint(Bp[t * 8]);
                uint32_t bq = __float_as_uint(Bp[t * 8 + 4 * NWST]);
                mma_tf32(acc[t], a0, a1, a2, a3, b0, bq);
            }
        }
    }
    {
        int row0 = rb + g, row1 = rb + g + 8;
        int n0 = nb + row0, n1 = nb + row1;
#pragma unroll
        for (int t = 0; t < 4; t++) {
            int nc = nb0 + t * 8 + 2 * tg;
            float2 bb = *(const float2*)&pb2[nc];
            if (n0 < NN) {
                float2 v;
                v.x = Xs[row0 * NXST + nc]     + acc[t][0] + bb.x;
                v.y = Xs[row0 * NXST + nc + 1] + acc[t][1] + bb.y;
                *(float2*)&out[(size_t)n0 * 64 + nc] = v;
            }
            if (n1 < NN) {
                float2 v;
                v.x = Xs[row1 * NXST + nc]     + acc[t][2] + bb.x;
                v.y = Xs[row1 * NXST + nc + 1] + acc[t][3] + bb.y;
                *(float2*)&out[(size_t)n1 * 64 + nc] = v;
            }
        }
    }
}

// ---------------------------------------------------------------------------
extern "C" void kernel_launch(void* const* d_in, const int* in_sizes, int n_in,
                              void* d_out, int out_size) {
    const float* h   = (const float*)d_in[0];
    const int*   ei  = (const int*)d_in[1];
    const float* eW1 = (const float*)d_in[2];
    const float* eb1 = (const float*)d_in[3];
    const float* eW2 = (const float*)d_in[4];
    const float* eb2 = (const float*)d_in[5];
    const float* qW1 = (const float*)d_in[6];
    const float* qb1 = (const float*)d_in[7];
    const float* qW2 = (const float*)d_in[8];
    const float* qb2 = (const float*)d_in[9];
    const float* pW1 = (const float*)d_in[10];
    const float* pb1 = (const float*)d_in[11];
    const float* pW2 = (const float*)d_in[12];
    const float* pb2 = (const float*)d_in[13];
    const float* al  = (const float*)d_in[14];
    const float* be  = (const float*)d_in[15];
    const float* ga  = (const float*)d_in[16];
    const float* de  = (const float*)d_in[17];
    const float* Lam = (const float*)d_in[18];

    float* out = (float*)d_out;
    float* mij = out + (size_t)NN * DD;

    cudaFuncSetAttribute(edge_kernel, cudaFuncAttributeMaxDynamicSharedMemorySize, EDGE_SMEM);
    cudaFuncSetAttribute(node_kernel, cudaFuncAttributeMaxDynamicSharedMemorySize, NODE_SMEM);

    zero_agg_kernel<<<(NN * DD / 4) / 256, 256>>>();
    edge_kernel<<<EDGE_GRID, 256, EDGE_SMEM>>>(h, ei, ei + NE, eW1, eb1, eW2, eb2, mij);
    node_kernel<<<(NN + 63) / 64, 256, NODE_SMEM>>>(h, qW1, qb1, qW2, qb2,
                                                    pW1, pb1, pW2, pb2,
                                                    al, be, ga, de, Lam, out);
}

// round 17
// speedup vs baseline: 3.5782x; 1.2341x over previous
#include <cuda_runtime.h>
#include <cuda_fp16.h>
#include <cstdint>

#define NN  50000
#define NE  800000
#define DD  64
#define HID 64
#define NTILES (NE / 64)
#define EDGE_GRID 296

// Scratch: aggregation buffer (allocation-free rule -> __device__ global)
__device__ float g_agg[NN * DD];

__device__ __forceinline__ float silu_f(float v) {
    return v * (1.0f / (1.0f + __expf(-v)));
}

// round fp32 -> tf32 (rna); value kept in a 32-bit float slot (node kernel)
__device__ __forceinline__ float tf32r(float x) {
    uint32_t u;
    asm("cvt.rna.tf32.f32 %0, %1;" : "=r"(u) : "f"(x));
    return __uint_as_float(u);
}
__device__ __forceinline__ uint32_t tf32u(float x) {
    uint32_t u;
    asm("cvt.rna.tf32.f32 %0, %1;" : "=r"(u) : "f"(x));
    return u;
}

// m16n8k8 tf32 MMA, fp32 accumulate (node kernel)
__device__ __forceinline__ void mma_tf32(float* c,
    uint32_t a0, uint32_t a1, uint32_t a2, uint32_t a3,
    uint32_t b0, uint32_t b1)
{
    asm volatile(
        "mma.sync.aligned.m16n8k8.row.col.f32.tf32.tf32.f32 "
        "{%0,%1,%2,%3}, {%4,%5,%6,%7}, {%8,%9}, {%0,%1,%2,%3};"
        : "+f"(c[0]), "+f"(c[1]), "+f"(c[2]), "+f"(c[3])
        : "r"(a0), "r"(a1), "r"(a2), "r"(a3), "r"(b0), "r"(b1));
}

// m16n8k16 fp16 MMA, fp32 accumulate (edge kernel)
__device__ __forceinline__ void mma_f16(float* c,
    uint32_t a0, uint32_t a1, uint32_t a2, uint32_t a3,
    uint32_t b0, uint32_t b1)
{
    asm volatile(
        "mma.sync.aligned.m16n8k16.row.col.f32.f16.f16.f32 "
        "{%0,%1,%2,%3}, {%4,%5,%6,%7}, {%8,%9}, {%0,%1,%2,%3};"
        : "+f"(c[0]), "+f"(c[1]), "+f"(c[2]), "+f"(c[3])
        : "r"(a0), "r"(a1), "r"(a2), "r"(a3), "r"(b0), "r"(b1));
}

__device__ __forceinline__ uint32_t h2u(__half2 h) {
    uint32_t u; memcpy(&u, &h, 4); return u;
}

// ---------------------------------------------------------------------------
// zero the aggregation scratch (must run every replay)
// ---------------------------------------------------------------------------
__global__ void zero_agg_kernel() {
    int i = blockIdx.x * blockDim.x + threadIdx.x;
    ((float4*)g_agg)[i] = make_float4(0.f, 0.f, 0.f, 0.f);
}

// ---------------------------------------------------------------------------
// Edge kernel (PERSISTENT, fp16 m16n8k16 tensor cores, fp32 accumulate):
// 296 blocks x 256 threads; weights packed to half2 once per block.
// Smem word strides: Xh 68 (bank 4g+tg), W 72 (bank 8tg+g), Hh 36.
// ---------------------------------------------------------------------------
#define XSTH 68   // uint32 words per X row (64 used)
#define WSTH 72   // uint32 words per W k-pair row (64 used)
#define HSTH 36   // uint32 words per H row (32 used)
#define EDGE_SMEM ((64*XSTH + 64*WSTH + 32*WSTH + 64*HSTH) * 4)

__global__ void __launch_bounds__(256, 2) edge_kernel(
    const float* __restrict__ h, const int* __restrict__ erow, const int* __restrict__ ecol,
    const float* __restrict__ W1, const float* __restrict__ b1,
    const float* __restrict__ W2, const float* __restrict__ b2,
    float* __restrict__ mij)
{
    extern __shared__ uint32_t smu[];
    uint32_t* Xh  = smu;                    // 64 x 68 words (half2 k-pairs)
    uint32_t* W1h = Xh + 64 * XSTH;         // 64 x 72 (k-pair, col)
    uint32_t* W2h = W1h + 64 * WSTH;        // 32 x 72
    uint32_t* Hh  = W2h + 32 * WSTH;        // 64 x 36

    const int tid = threadIdx.x;

    // pack W1 [128x64] -> W1h[kw][c] = half2(W1[2kw][c], W1[2kw+1][c])  (once)
    for (int idx = tid; idx < 64 * 64; idx += 256) {
        int kw = idx >> 6, c = idx & 63;
        __half2 hv = __floats2half2_rn(W1[(2 * kw) * 64 + c], W1[(2 * kw + 1) * 64 + c]);
        W1h[kw * WSTH + c] = h2u(hv);
    }
    for (int idx = tid; idx < 32 * 64; idx += 256) {
        int kw = idx >> 6, c = idx & 63;
        __half2 hv = __floats2half2_rn(W2[(2 * kw) * 64 + c], W2[(2 * kw + 1) * 64 + c]);
        W2h[kw * WSTH + c] = h2u(hv);
    }

    const int warp = tid >> 5, lane = tid & 31;
    const int rb  = (warp >> 1) * 16;    // row-tile base
    const int nb0 = (warp & 1) * 32;     // col-half base
    const int g   = lane >> 2, tg = lane & 3;
    const float4* h4 = (const float4*)h;

    // biases are loop-invariant: hoist
    float2 b1v[4], b2v[4];
#pragma unroll
    for (int t = 0; t < 4; t++) {
        int nc = nb0 + t * 8 + 2 * tg;
        b1v[t] = *(const float2*)&b1[nc];
        b2v[t] = *(const float2*)&b2[nc];
    }

    // per-thread gather geometry (fixed across tiles)
    int grow[8], gpos[8];
#pragma unroll
    for (int i = 0; i < 8; i++) {
        int f = i * 256 + tid;
        grow[i] = f >> 5;        // tile-local edge row 0..63
        gpos[i] = f & 31;        // float4 slot within 128-float row
    }

    // prefetch first tile into registers
    float4 pf[8];
    int tile = blockIdx.x;
    if (tile < NTILES) {
        int eb = tile * 64;
#pragma unroll
        for (int i = 0; i < 8; i++) {
            int node = (gpos[i] < 16) ? erow[eb + grow[i]] : ecol[eb + grow[i]];
            pf[i] = h4[node * 16 + (gpos[i] & 15)];
        }
    }
    __syncthreads();   // weights staged

    for (; tile < NTILES; tile += EDGE_GRID) {
        // store prefetched X (fp16-packed) -> Xh
#pragma unroll
        for (int i = 0; i < 8; i++) {
            float4 v = pf[i];
            uint2 st;
            st.x = h2u(__floats2half2_rn(v.x, v.y));
            st.y = h2u(__floats2half2_rn(v.z, v.w));
            *(uint2*)&Xh[grow[i] * XSTH + gpos[i] * 2] = st;
        }
        __syncthreads();   // Xh ready; prev iter's Hh reads done

        // issue prefetch for next tile (hidden behind both layers)
        int nt = tile + EDGE_GRID;
        if (nt < NTILES) {
            int eb2 = nt * 64;
#pragma unroll
            for (int i = 0; i < 8; i++) {
                int node = (gpos[i] < 16) ? erow[eb2 + grow[i]] : ecol[eb2 + grow[i]];
                pf[i] = h4[node * 16 + (gpos[i] & 15)];
            }
        }

        float acc[4][4];
#pragma unroll
        for (int t = 0; t < 4; t++)
#pragma unroll
            for (int j = 0; j < 4; j++) acc[t][j] = 0.f;

        // layer 1: [64x128] @ [128x64], k16 per mma (8 steps)
        {
            const uint32_t* A0 = Xh + (rb + g) * XSTH + tg;
            const uint32_t* A1 = Xh + (rb + g + 8) * XSTH + tg;
#pragma unroll
            for (int kk = 0; kk < 8; kk++) {
                int k0 = kk * 8;                 // word offset (16 halves)
                uint32_t a0 = A0[k0];
                uint32_t a1 = A1[k0];
                uint32_t a2 = A0[k0 + 4];
                uint32_t a3 = A1[k0 + 4];
                const uint32_t* Bp = W1h + (k0 + tg) * WSTH + nb0 + g;
#pragma unroll
                for (int t = 0; t < 4; t++) {
                    uint32_t b0 = Bp[t * 8];
                    uint32_t bq = Bp[t * 8 + 4 * WSTH];
                    mma_f16(acc[t], a0, a1, a2, a3, b0, bq);
                }
            }
        }
        // epilogue 1: bias + silu -> Hh (half2-packed)
#pragma unroll
        for (int t = 0; t < 4; t++) {
            int wc = (nb0 >> 1) + t * 4 + tg;   // word column
            __half2 v0 = __floats2half2_rn(silu_f(acc[t][0] + b1v[t].x),
                                           silu_f(acc[t][1] + b1v[t].y));
            __half2 v1 = __floats2half2_rn(silu_f(acc[t][2] + b1v[t].x),
                                           silu_f(acc[t][3] + b1v[t].y));
            Hh[(rb + g) * HSTH + wc]     = h2u(v0);
            Hh[(rb + g + 8) * HSTH + wc] = h2u(v1);
        }
        __syncthreads();   // Hh ready; Xh free for next iter's STS

#pragma unroll
        for (int t = 0; t < 4; t++)
#pragma unroll
            for (int j = 0; j < 4; j++) acc[t][j] = 0.f;

        // layer 2: [64x64] @ [64x64], k16 per mma (4 steps)
        {
            const uint32_t* A0 = Hh + (rb + g) * HSTH + tg;
            const uint32_t* A1 = Hh + (rb + g + 8) * HSTH + tg;
#pragma unroll
            for (int kk = 0; kk < 4; kk++) {
                int k0 = kk * 8;
                uint32_t a0 = A0[k0];
                uint32_t a1 = A1[k0];
                uint32_t a2 = A0[k0 + 4];
                uint32_t a3 = A1[k0 + 4];
                const uint32_t* Bp = W2h + (k0 + tg) * WSTH + nb0 + g;
#pragma unroll
                for (int t = 0; t < 4; t++) {
                    uint32_t b0 = Bp[t * 8];
                    uint32_t bq = Bp[t * 8 + 4 * WSTH];
                    mma_f16(acc[t], a0, a1, a2, a3, b0, bq);
                }
            }
        }
        // epilogue 2: bias + silu -> mij (float2) + scatter-add into g_agg
        {
            int eb = tile * 64;
            int row0 = rb + g, row1 = rb + g + 8;
            int nd0 = erow[eb + row0], nd1 = erow[eb + row1];
            size_t ge0 = (size_t)(eb + row0) * 64;
            size_t ge1 = (size_t)(eb + row1) * 64;
#pragma unroll
            for (int t = 0; t < 4; t++) {
                int nc = nb0 + t * 8 + 2 * tg;
                float2 m0, m1;
                m0.x = silu_f(acc[t][0] + b2v[t].x);
                m0.y = silu_f(acc[t][1] + b2v[t].y);
                m1.x = silu_f(acc[t][2] + b2v[t].x);
                m1.y = silu_f(acc[t][3] + b2v[t].y);
                *(float2*)&mij[ge0 + nc] = m0;
                *(float2*)&mij[ge1 + nc] = m1;
                asm volatile("red.global.add.v2.f32 [%0], {%1,%2};"
                             :: "l"(&g_agg[(size_t)nd0 * 64 + nc]), "f"(m0.x), "f"(m0.y) : "memory");
                asm volatile("red.global.add.v2.f32 [%0], {%1,%2};"
                             :: "l"(&g_agg[(size_t)nd1 * 64 + nc]), "f"(m1.x), "f"(m1.y) : "memory");
            }
        }
        // no sync: STS->Xh gated by mid-sync; Hh overwrite gated by top sync.
    }
}

// ---------------------------------------------------------------------------
// 3-qubit statevector circuit (per node, per thread)
// ---------------------------------------------------------------------------
__device__ __forceinline__ void apply_rx3(float* ar, float* ai, float cb, float sb) {
#pragma unroll
    for (int q = 0; q < 3; q++) {
        int st = 4 >> q;
#pragma unroll
        for (int i = 0; i < 8; i++) {
            if (i & st) continue;
            int j = i + st;
            float a0r = ar[i], a0i = ai[i], a1r = ar[j], a1i = ai[j];
            ar[i] =  cb * a0r + sb * a1i;
            ai[i] =  cb * a0i - sb * a1r;
            ar[j] =  sb * a0i + cb * a1r;
            ai[j] = -sb * a0r + cb * a1i;
        }
    }
}

__device__ __forceinline__ void apply_rz(float* ar, float* ai, int st, float theta) {
    float s, c;
    sincosf(0.5f * theta, &s, &c);
#pragma unroll
    for (int i = 0; i < 8; i++) {
        float r = ar[i], im = ai[i];
        if (i & st) { ar[i] = r * c - im * s; ai[i] = im * c + r * s; }
        else        { ar[i] = r * c + im * s; ai[i] = im * c - r * s; }
    }
}

__device__ __forceinline__ void apply_h(float* ar, float* ai, int st) {
    const float SQ = 0.70710678118654752f;
#pragma unroll
    for (int i = 0; i < 8; i++) {
        if (i & st) continue;
        int j = i + st;
        float a0r = ar[i], a0i = ai[i], a1r = ar[j], a1i = ai[j];
        ar[i] = (a0r + a1r) * SQ; ai[i] = (a0i + a1i) * SQ;
        ar[j] = (a0r - a1r) * SQ; ai[j] = (a0i - a1i) * SQ;
    }
}

__device__ void qcircuit(const float* x, float alpha, float beta, float gamma, float delta,
                         const float* __restrict__ Lam, float* outq)
{
    float ar[8], ai[8];
#pragma unroll
    for (int i = 0; i < 8; i++) { ar[i] = 0.f; ai[i] = 0.f; }
    ar[0] = 1.f;

#pragma unroll
    for (int q = 0; q < 3; q++) {
        float s, c;
        sincosf(0.5f * alpha * x[q], &s, &c);
        int st = 4 >> q;
#pragma unroll
        for (int i = 0; i < 8; i++) {
            if (i & st) continue;
            int j = i + st;
            float a0r = ar[i], a0i = ai[i], a1r = ar[j], a1i = ai[j];
            ar[i] = c * a0r - s * a1r; ai[i] = c * a0i - s * a1i;
            ar[j] = s * a0r + c * a1r; ai[j] = s * a0i + c * a1i;
        }
    }
#pragma unroll
    for (int qi = 0; qi < 3; qi++)
#pragma unroll
        for (int qj = qi + 1; qj < 3; qj++) {
            float phi = 0.5f * gamma * (Lam[qi * 3 + qj] + Lam[qj * 3 + qi]);
            float sp, cp;
            sincosf(0.5f * phi, &sp, &cp);
#pragma unroll
            for (int i = 0; i < 8; i++) {
                int bi = (i >> (2 - qi)) & 1, bj = (i >> (2 - qj)) & 1;
                float pi = (bi ^ bj) ? sp : -sp;
                float r = ar[i] * cp - ai[i] * pi;
                ai[i]   = ar[i] * pi + ai[i] * cp;
                ar[i]   = r;
            }
        }
    float sb, cb;
    sincosf(0.5f * beta, &sb, &cb);
    apply_rx3(ar, ai, cb, sb);
#pragma unroll
    for (int q = 0; q < 3; q++) {
        int st = 4 >> q;
        float x2 = x[q] * x[q];
        apply_rz(ar, ai, st, delta * (1.f - 0.5f * x2));
        apply_h(ar, ai, st);
        apply_rz(ar, ai, st, delta * x2);
        apply_h(ar, ai, st);
    }
    apply_rx3(ar, ai, cb, sb);

    float e0 = 0.f, e1 = 0.f, e2 = 0.f;
#pragma unroll
    for (int i = 0; i < 8; i++) {
        float p = ar[i] * ar[i] + ai[i] * ai[i];
        e0 += (i & 4) ? -p : p;
        e1 += (i & 2) ? -p : p;
        e2 += (i & 1) ? -p : p;
    }
    outq[0] = e0; outq[1] = e1; outq[2] = e2;
}

// ---------------------------------------------------------------------------
// Node kernel (tensor-core tf32): 64 nodes/block, 256 threads (8 warps).
// Xs kept fp32 (exact residual + circuit I/O); A-operands cvt-on-load.
// ---------------------------------------------------------------------------
#define NXST 132
#define NWST 72
#define NHST 68
#define NODE_SMEM ((64*NXST + 131*NWST + 64*NHST) * 4)

__global__ void __launch_bounds__(256, 2) node_kernel(
    const float* __restrict__ h,
    const float* __restrict__ qW1, const float* __restrict__ qb1,
    const float* __restrict__ qW2, const float* __restrict__ qb2,
    const float* __restrict__ pW1, const float* __restrict__ pb1,
    const float* __restrict__ pW2, const float* __restrict__ pb2,
    const float* __restrict__ alpha_p, const float* __restrict__ beta_p,
    const float* __restrict__ gamma_p, const float* __restrict__ delta_p,
    const float* __restrict__ Lam,
    float* __restrict__ out)
{
    extern __shared__ float sm[];
    float* Xs = sm;                 // 64 x 132 fp32: [h(64) | agg/100(64) | q_out(3) | pad]
    float* Ws = Xs + 64 * NXST;     // up to 131 x 72 (tf32-rounded weights)
    float* Hs = Ws + 131 * NWST;    // 64 x 68

    const int tid = threadIdx.x;
    const int nb  = blockIdx.x * 64;

    // gather X (fp32, unrounded)
    const float4* h4 = (const float4*)h;
    const float4* a4 = (const float4*)g_agg;
#pragma unroll
    for (int i = 0; i < 8; i++) {
        int f = i * 256 + tid;
        int r = f >> 5, p = f & 31;
        int node = nb + r;
        float4 v = make_float4(0.f, 0.f, 0.f, 0.f);
        if (node < NN) {
            if (p < 16) v = h4[node * 16 + p];
            else {
                v = a4[node * 16 + (p - 16)];
                v.x *= 0.01f; v.y *= 0.01f; v.z *= 0.01f; v.w *= 0.01f;
            }
        }
        ((float4*)Xs)[r * 33 + p] = v;
    }
    if (tid < 64) ((float4*)Xs)[tid * 33 + 32] = make_float4(0.f, 0.f, 0.f, 0.f);

    // stage qW1 [128x72], tf32-rounded
#pragma unroll
    for (int i = 0; i < 8; i++) {
        int f = i * 256 + tid;
        int k = f >> 4, c = f & 15;
        float4 v = ((const float4*)qW1)[f];
        v.x = tf32r(v.x); v.y = tf32r(v.y); v.z = tf32r(v.z); v.w = tf32r(v.w);
        ((float4*)Ws)[k * 18 + c] = v;
    }
    __syncthreads();

    const int warp = tid >> 5, lane = tid & 31;
    const int rb  = (warp >> 1) * 16;
    const int nb0 = (warp & 1) * 32;
    const int g   = lane >> 2, tg = lane & 3;

    float acc[4][4];
#pragma unroll
    for (int t = 0; t < 4; t++)
#pragma unroll
        for (int j = 0; j < 4; j++) acc[t][j] = 0.f;

    // phase A: H = silu(X[:, :128] @ qW1 + qb1)
    {
        const float* A0 = Xs + (rb + g) * NXST + tg;
        const float* A1 = Xs + (rb + g + 8) * NXST + tg;
#pragma unroll
        for (int kk = 0; kk < 16; kk++) {
            int k0 = kk * 8;
            uint32_t a0 = tf32u(A0[k0]);
            uint32_t a1 = tf32u(A1[k0]);
            uint32_t a2 = tf32u(A0[k0 + 4]);
            uint32_t a3 = tf32u(A1[k0 + 4]);
            const float* Bp = Ws + (k0 + tg) * NWST + nb0 + g;
#pragma unroll
            for (int t = 0; t < 4; t++) {
                uint32_t b0 = __float_as_uint(Bp[t * 8]);
                uint32_t bq = __float_as_uint(Bp[t * 8 + 4 * NWST]);
                mma_tf32(acc[t], a0, a1, a2, a3, b0, bq);
            }
        }
    }
#pragma unroll
    for (int t = 0; t < 4; t++) {
        int nc = nb0 + t * 8 + 2 * tg;
        float2 bb = *(const float2*)&qb1[nc];
        float2 v0, v1;
        v0.x = silu_f(acc[t][0] + bb.x);
        v0.y = silu_f(acc[t][1] + bb.y);
        v1.x = silu_f(acc[t][2] + bb.x);
        v1.y = silu_f(acc[t][3] + bb.y);
        *(float2*)&Hs[(rb + g) * NHST + nc]     = v0;
        *(float2*)&Hs[(rb + g + 8) * NHST + nc] = v1;
    }
    __syncthreads();

    // phase B: q_in = H @ qW2 + qb2 ; quantum circuit (one thread per node)
    if (tid < 64) {
        float qin[3] = { qb2[0], qb2[1], qb2[2] };
        for (int k = 0; k < 64; k++) {
            float hv = Hs[tid * NHST + k];
            qin[0] += hv * qW2[k * 3 + 0];
            qin[1] += hv * qW2[k * 3 + 1];
            qin[2] += hv * qW2[k * 3 + 2];
        }
        float qo[3];
        qcircuit(qin, *alpha_p, *beta_p, *gamma_p, *delta_p, Lam, qo);
        Xs[tid * NXST + 128] = qo[0];
        Xs[tid * NXST + 129] = qo[1];
        Xs[tid * NXST + 130] = qo[2];
    }
    __syncthreads();

    // stage pW1 [131x72], tf32-rounded
    for (int f = tid; f < 131 * 16; f += 256) {
        int k = f >> 4, c = f & 15;
        float4 v = ((const float4*)pW1)[f];
        v.x = tf32r(v.x); v.y = tf32r(v.y); v.z = tf32r(v.z); v.w = tf32r(v.w);
        ((float4*)Ws)[k * 18 + c] = v;
    }
    __syncthreads();

    // phase C: P = silu(X[:, :131] @ pW1 + pb1)  (MMA k=0..127 + fp32 tail)
#pragma unroll
    for (int t = 0; t < 4; t++)
#pragma unroll
        for (int j = 0; j < 4; j++) acc[t][j] = 0.f;
    {
        const float* A0 = Xs + (rb + g) * NXST + tg;
        const float* A1 = Xs + (rb + g + 8) * NXST + tg;
#pragma unroll
        for (int kk = 0; kk < 16; kk++) {
            int k0 = kk * 8;
            uint32_t a0 = tf32u(A0[k0]);
            uint32_t a1 = tf32u(A1[k0]);
            uint32_t a2 = tf32u(A0[k0 + 4]);
            uint32_t a3 = tf32u(A1[k0 + 4]);
            const float* Bp = Ws + (k0 + tg) * NWST + nb0 + g;
#pragma unroll
            for (int t = 0; t < 4; t++) {
                uint32_t b0 = __float_as_uint(Bp[t * 8]);
                uint32_t bq = __float_as_uint(Bp[t * 8 + 4 * NWST]);
                mma_tf32(acc[t], a0, a1, a2, a3, b0, bq);
            }
        }
        // fp32 tail k = 128..130 (q_out columns)
#pragma unroll
        for (int k = 128; k < 131; k++) {
            float xa = Xs[(rb + g) * NXST + k];
            float xb = Xs[(rb + g + 8) * NXST + k];
#pragma unroll
            for (int t = 0; t < 4; t++) {
                int nc = nb0 + t * 8 + 2 * tg;
                float w0 = Ws[k * NWST + nc];
                float w1 = Ws[k * NWST + nc + 1];
                acc[t][0] += xa * w0; acc[t][1] += xa * w1;
                acc[t][2] += xb * w0; acc[t][3] += xb * w1;
            }
        }
    }
#pragma unroll
    for (int t = 0; t < 4; t++) {
        int nc = nb0 + t * 8 + 2 * tg;
        float2 bb = *(const float2*)&pb1[nc];
        float2 v0, v1;
        v0.x = tf32r(silu_f(acc[t][0] + bb.x));
        v0.y = tf32r(silu_f(acc[t][1] + bb.y));
        v1.x = tf32r(silu_f(acc[t][2] + bb.x));
        v1.y = tf32r(silu_f(acc[t][3] + bb.y));
        *(float2*)&Hs[(rb + g) * NHST + nc]     = v0;
        *(float2*)&Hs[(rb + g + 8) * NHST + nc] = v1;
    }
    __syncthreads();

    // stage pW2 [64x72], tf32-rounded
    for (int f = tid; f < 64 * 16; f += 256) {
        int k = f >> 4, c = f & 15;
        float4 v = ((const float4*)pW2)[f];
        v.x = tf32r(v.x); v.y = tf32r(v.y); v.z = tf32r(v.z); v.w = tf32r(v.w);
        ((float4*)Ws)[k * 18 + c] = v;
    }
    __syncthreads();

    // phase D: out = h + P @ pW2 + pb2
#pragma unroll
    for (int t = 0; t < 4; t++)
#pragma unroll
        for (int j = 0; j < 4; j++) acc[t][j] = 0.f;
    {
        const float* A0 = Hs + (rb + g) * NHST + tg;
        const float* A1 = Hs + (rb + g + 8) * NHST + tg;
#pragma unroll
        for (int kk = 0; kk < 8; kk++) {
            int k0 = kk * 8;
            uint32_t a0 = __float_as_uint(A0[k0]);
            uint32_t a1 = __float_as_uint(A1[k0]);
            uint32_t a2 = __float_as_uint(A0[k0 + 4]);
            uint32_t a3 = __float_as_uint(A1[k0 + 4]);
            const float* Bp = Ws + (k0 + tg) * NWST + nb0 + g;
#pragma unroll
            for (int t = 0; t < 4; t++) {
                uint32_t b0 = __float_as_uint(Bp[t * 8]);
                uint32_t bq = __float_as_uint(Bp[t * 8 + 4 * NWST]);
                mma_tf32(acc[t], a0, a1, a2, a3, b0, bq);
            }
        }
    }
    {
        int row0 = rb + g, row1 = rb + g + 8;
        int n0 = nb + row0, n1 = nb + row1;
#pragma unroll
        for (int t = 0; t < 4; t++) {
            int nc = nb0 + t * 8 + 2 * tg;
            float2 bb = *(const float2*)&pb2[nc];
            if (n0 < NN) {
                float2 v;
                v.x = Xs[row0 * NXST + nc]     + acc[t][0] + bb.x;
                v.y = Xs[row0 * NXST + nc + 1] + acc[t][1] + bb.y;
                *(float2*)&out[(size_t)n0 * 64 + nc] = v;
            }
            if (n1 < NN) {
                float2 v;
                v.x = Xs[row1 * NXST + nc]     + acc[t][2] + bb.x;
                v.y = Xs[row1 * NXST + nc + 1] + acc[t][3] + bb.y;
                *(float2*)&out[(size_t)n1 * 64 + nc] = v;
            }
        }
    }
}

// ---------------------------------------------------------------------------
extern "C" void kernel_launch(void* const* d_in, const int* in_sizes, int n_in,
                              void* d_out, int out_size) {
    const float* h   = (const float*)d_in[0];
    const int*   ei  = (const int*)d_in[1];
    const float* eW1 = (const float*)d_in[2];
    const float* eb1 = (const float*)d_in[3];
    const float* eW2 = (const float*)d_in[4];
    const float* eb2 = (const float*)d_in[5];
    const float* qW1 = (const float*)d_in[6];
    const float* qb1 = (const float*)d_in[7];
    const float* qW2 = (const float*)d_in[8];
    const float* qb2 = (const float*)d_in[9];
    const float* pW1 = (const float*)d_in[10];
    const float* pb1 = (const float*)d_in[11];
    const float* pW2 = (const float*)d_in[12];
    const float* pb2 = (const float*)d_in[13];
    const float* al  = (const float*)d_in[14];
    const float* be  = (const float*)d_in[15];
    const float* ga  = (const float*)d_in[16];
    const float* de  = (const float*)d_in[17];
    const float* Lam = (const float*)d_in[18];

    float* out = (float*)d_out;
    float* mij = out + (size_t)NN * DD;

    cudaFuncSetAttribute(edge_kernel, cudaFuncAttributeMaxDynamicSharedMemorySize, EDGE_SMEM);
    cudaFuncSetAttribute(node_kernel, cudaFuncAttributeMaxDynamicSharedMemorySize, NODE_SMEM);

    zero_agg_kernel<<<(NN * DD / 4) / 256, 256>>>();
    edge_kernel<<<EDGE_GRID, 256, EDGE_SMEM>>>(h, ei, ei + NE, eW1, eb1, eW2, eb2, mij);
    node_kernel<<<(NN + 63) / 64, 256, NODE_SMEM>>>(h, qW1, qb1, qW2, qb2,
                                                    pW1, pb1, pW2, pb2,
                                                    al, be, ga, de, Lam, out);
}